// round 15
// baseline (speedup 1.0000x reference)
#include <cuda_runtime.h>
#include <cuda_bf16.h>
#include <cuda_fp16.h>
#include <math.h>
#include <stdint.h>

// Problem constants
#define PB   2
#define PS   2048
#define PHID 2048
#define PH   16
#define PD   128
#define PM   (PB * PS)          // 4096 rows
#define QSCALE 11.313708498984760f   // sqrt(128)

// ---------------------------------------------------------------------------
// Scratch (no cudaMalloc allowed)
// ---------------------------------------------------------------------------
__device__ __nv_bfloat16 g_xh[(size_t)PM * PHID];    // x split bf16 (QK path)
__device__ __nv_bfloat16 g_xl[(size_t)PM * PHID];
__device__ __half        g_xh2[(size_t)PM * PHID];   // x split fp16 (V path)
__device__ __half        g_xl2[(size_t)PM * PHID];
__device__ __nv_bfloat16 g_qh[(size_t)PM * PHID];
__device__ __nv_bfloat16 g_ql[(size_t)PM * PHID];
__device__ __nv_bfloat16 g_kh[(size_t)PM * PHID];
__device__ __nv_bfloat16 g_kl[(size_t)PM * PHID];
__device__ __half        g_vhf[(size_t)PM * PHID];   // V, fp16
__device__ __half        g_ch2[(size_t)PM * PHID];   // ctx split fp16
__device__ __half        g_cl2[(size_t)PM * PHID];

// transposed weights [N,K]
__device__ __nv_bfloat16 g_wqh[(size_t)PHID * PHID];
__device__ __nv_bfloat16 g_wql[(size_t)PHID * PHID];
__device__ __nv_bfloat16 g_wkh[(size_t)PHID * PHID];
__device__ __nv_bfloat16 g_wkl[(size_t)PHID * PHID];
__device__ __half        g_wvt[(size_t)PHID * PHID]; // Wv^T single fp16
__device__ __half        g_wot[(size_t)PHID * PHID]; // Wo^T single fp16

// ---------------------------------------------------------------------------
// Helpers
// ---------------------------------------------------------------------------
__device__ __forceinline__ uint32_t smem_u32(const void* p) {
    uint32_t a;
    asm("{ .reg .u64 t; cvta.to.shared.u64 t, %1; cvt.u32.u64 %0, t; }"
        : "=r"(a) : "l"(p));
    return a;
}

__device__ __forceinline__ void cp16(uint32_t s, const void* g) {
    asm volatile("cp.async.cg.shared.global [%0], [%1], 16;" :: "r"(s), "l"(g));
}
#define CP_COMMIT() asm volatile("cp.async.commit_group;" ::: "memory")
#define CP_WAIT(n)  asm volatile("cp.async.wait_group %0;" :: "n"(n) : "memory")

__device__ __forceinline__ void ldm_x4(uint32_t* r, uint32_t addr) {
    asm volatile("ldmatrix.sync.aligned.m8n8.x4.shared.b16 {%0,%1,%2,%3}, [%4];"
                 : "=r"(r[0]), "=r"(r[1]), "=r"(r[2]), "=r"(r[3]) : "r"(addr));
}
__device__ __forceinline__ void ldm_x4t(uint32_t* r, uint32_t addr) {
    asm volatile("ldmatrix.sync.aligned.m8n8.x4.trans.shared.b16 {%0,%1,%2,%3}, [%4];"
                 : "=r"(r[0]), "=r"(r[1]), "=r"(r[2]), "=r"(r[3]) : "r"(addr));
}
__device__ __forceinline__ void mma_bf16(float* c, const uint32_t* a, const uint32_t* b) {
    asm volatile(
        "mma.sync.aligned.m16n8k16.row.col.f32.bf16.bf16.f32 "
        "{%0,%1,%2,%3}, {%4,%5,%6,%7}, {%8,%9}, {%0,%1,%2,%3};"
        : "+f"(c[0]), "+f"(c[1]), "+f"(c[2]), "+f"(c[3])
        : "r"(a[0]), "r"(a[1]), "r"(a[2]), "r"(a[3]), "r"(b[0]), "r"(b[1]));
}
__device__ __forceinline__ void mma_f16(float* c, const uint32_t* a, const uint32_t* b) {
    asm volatile(
        "mma.sync.aligned.m16n8k16.row.col.f32.f16.f16.f32 "
        "{%0,%1,%2,%3}, {%4,%5,%6,%7}, {%8,%9}, {%0,%1,%2,%3};"
        : "+f"(c[0]), "+f"(c[1]), "+f"(c[2]), "+f"(c[3])
        : "r"(a[0]), "r"(a[1]), "r"(a[2]), "r"(a[3]), "r"(b[0]), "r"(b[1]));
}

__device__ __forceinline__ float ex2f(float x) {
    float r;
    asm("ex2.approx.f32 %0, %1;" : "=f"(r) : "f"(x));
    return r;
}

// pack two fp32 exponent args into f16x2 and take 2^x on both at once
__device__ __forceinline__ uint32_t h2ex2(float y0, float y1) {
    uint32_t h, p;
    asm("cvt.rn.f16x2.f32 %0, %1, %2;" : "=r"(h) : "f"(y1), "f"(y0));
    asm("ex2.approx.f16x2 %0, %1;" : "=r"(p) : "r"(h));
    return p;
}

// Fast RNE split of two floats into (hi bf16x2, lo bf16x2).
__device__ __forceinline__ void packsplit(float a, float b, uint32_t& hp, uint32_t& lp) {
    asm("cvt.rn.bf16x2.f32 %0, %1, %2;" : "=r"(hp) : "f"(b), "f"(a));
    float ah = __uint_as_float(hp << 16);
    float bh = __uint_as_float(hp & 0xFFFF0000u);
    float la = a - ah;
    float lb = b - bh;
    asm("cvt.rn.bf16x2.f32 %0, %1, %2;" : "=r"(lp) : "f"(lb), "f"(la));
}

// RNE split of two floats into (hi f16x2, lo f16x2).
__device__ __forceinline__ void packsplit_f16(float a, float b, uint32_t& hp, uint32_t& lp) {
    __half2 h = __floats2half2_rn(a, b);
    float la = a - __half2float(__low2half(h));
    float lb = b - __half2float(__high2half(h));
    __half2 l = __floats2half2_rn(la, lb);
    hp = *reinterpret_cast<uint32_t*>(&h);
    lp = *reinterpret_cast<uint32_t*>(&l);
}

// ---------------------------------------------------------------------------
// Conversion kernels
// ---------------------------------------------------------------------------
__global__ void split_x_kernel(const float* __restrict__ in,
                               __nv_bfloat16* __restrict__ hb,
                               __nv_bfloat16* __restrict__ lb,
                               __half* __restrict__ hf,
                               __half* __restrict__ lf, int n4)
{
    int i = blockIdx.x * blockDim.x + threadIdx.x;
    if (i >= n4) return;
    float4 v = ((const float4*)in)[i];
    uint32_t h0, l0, h1, l1;
    packsplit(v.x, v.y, h0, l0);
    packsplit(v.z, v.w, h1, l1);
    ((uint32_t*)hb)[2*i]   = h0;
    ((uint32_t*)hb)[2*i+1] = h1;
    ((uint32_t*)lb)[2*i]   = l0;
    ((uint32_t*)lb)[2*i+1] = l1;
    packsplit_f16(v.x, v.y, h0, l0);
    packsplit_f16(v.z, v.w, h1, l1);
    ((uint32_t*)hf)[2*i]   = h0;
    ((uint32_t*)hf)[2*i+1] = h1;
    ((uint32_t*)lf)[2*i]   = l0;
    ((uint32_t*)lf)[2*i+1] = l1;
}

// One launch transposes all 4 weight matrices.  z=0,1 -> bf16 split (Wq, Wk);
// z=2,3 -> single fp16 (Wv, Wo).
__global__ void transpose_all_kernel(
    const float* __restrict__ Wq, const float* __restrict__ Wk,
    const float* __restrict__ Wv, const float* __restrict__ Wo,
    __nv_bfloat16* __restrict__ Tqh, __nv_bfloat16* __restrict__ Tql,
    __nv_bfloat16* __restrict__ Tkh, __nv_bfloat16* __restrict__ Tkl,
    __half* __restrict__ Tv, __half* __restrict__ To)
{
    __shared__ float t[32][33];
    int z = blockIdx.z;
    const float* W = (z == 0) ? Wq : (z == 1) ? Wk : (z == 2) ? Wv : Wo;
    int n0 = blockIdx.x * 32, k0 = blockIdx.y * 32;
    int tx = threadIdx.x, ty0 = threadIdx.y;   // 32 x 8
#pragma unroll
    for (int j = 0; j < 32; j += 8)
        t[ty0 + j][tx] = W[(size_t)(k0 + ty0 + j) * PHID + n0 + tx];
    __syncthreads();
#pragma unroll
    for (int j = 0; j < 32; j += 8) {
        int n = ty0 + j;
        float v = t[tx][n];
        size_t o = (size_t)(n0 + n) * PHID + k0 + tx;
        if (z < 2) {
            __nv_bfloat16 h = __float2bfloat16(v);
            __nv_bfloat16 l = __float2bfloat16(v - __bfloat162float(h));
            if (z == 0) { Tqh[o] = h; Tql[o] = l; }
            else        { Tkh[o] = h; Tkl[o] = l; }
        } else {
            __half h = __float2half_rn(v);
            if (z == 2) Tv[o] = h; else To[o] = h;
        }
    }
}

// ---------------------------------------------------------------------------
// GEMM tile configs
// ---------------------------------------------------------------------------
// gemm_qk 4-stage BK=16 ring: tile = 128 rows x 48B (16 bf16 + 8 pad)
#define QK_TILE  6144
#define QK_AH    0
#define QK_AL    (QK_TILE)
#define QK_BH    (2 * QK_TILE)
#define QK_BL    (3 * QK_TILE)
#define QK_STAGE (4 * QK_TILE)   // 24576
#define QK_SMEM  (4 * QK_STAGE)  // 98304

// gemm_f16_2c 4-stage BK=16 ring: 3 tiles (Ah, Al, B) of 128 x 48B
#define F2_TILE  6144
#define F2_AH    0
#define F2_AL    (F2_TILE)
#define F2_B     (2 * F2_TILE)
#define F2_STAGE (3 * F2_TILE)   // 18432
#define F2_SMEM  (4 * F2_STAGE)  // 73728

// ---------------------------------------------------------------------------
// Q/K projection GEMM (split-bf16, 3 combos): sel = blockIdx.x>>4 in {0,1}.
// 4-stage BK=16 ring, ONE __syncthreads per chunk, 3-chunk prefetch.
// ---------------------------------------------------------------------------
__global__ __launch_bounds__(256, 2) void gemm_qk(
    const __nv_bfloat16* __restrict__ Ah, const __nv_bfloat16* __restrict__ Al,
    const __nv_bfloat16* __restrict__ Wqh, const __nv_bfloat16* __restrict__ Wql,
    const __nv_bfloat16* __restrict__ Wkh, const __nv_bfloat16* __restrict__ Wkl,
    const float* __restrict__ bq, const float* __restrict__ bk,
    __nv_bfloat16* __restrict__ Qh, __nv_bfloat16* __restrict__ Ql,
    __nv_bfloat16* __restrict__ Kh, __nv_bfloat16* __restrict__ Kl)
{
    extern __shared__ char smem[];
    const uint32_t sb = smem_u32(smem);
    const int tid  = threadIdx.x;
    const int lane = tid & 31;
    const int warp = tid >> 5;
    const int wm = warp >> 2;
    const int wn = warp & 3;
    const int sel = blockIdx.x >> 4;            // 0=Q 1=K
    const int n0  = (blockIdx.x & 15) * 128;
    const int m0  = blockIdx.y * 128;

    const __nv_bfloat16* Bh = sel ? Wkh : Wqh;
    const __nv_bfloat16* Bl = sel ? Wkl : Wql;
    const float* bias = sel ? bk : bq;
    const float scale = sel ? 1.0f : QSCALE;

    const __nv_bfloat16* pAh = Ah + (size_t)m0 * PHID;
    const __nv_bfloat16* pAl = Al + (size_t)m0 * PHID;
    const __nv_bfloat16* pBh = Bh + (size_t)n0 * PHID;
    const __nv_bfloat16* pBl = Bl + (size_t)n0 * PHID;

    const int r0 = tid >> 1;               // 0..127
    const int ce = (tid & 1) * 8;
    const uint32_t so = (uint32_t)(r0 * 48 + (tid & 1) * 16);

    const uint32_t a_off = (uint32_t)((wm * 64 + (lane & 15)) * 48 + ((lane >> 4) << 4));
    const uint32_t b4_off = (uint32_t)((wn * 32 + ((lane >> 4) << 3) + (lane & 7)) * 48
                                       + ((lane & 8) ? 16 : 0));

    float acc[4][4][4];
#pragma unroll
    for (int mi = 0; mi < 4; mi++)
#pragma unroll
        for (int ni = 0; ni < 4; ni++)
#pragma unroll
            for (int j = 0; j < 4; j++) acc[mi][ni][j] = 0.0f;

    auto load_stage = [&](int stage, int kc) {
        const uint32_t st = sb + stage * QK_STAGE;
        const size_t g = (size_t)r0 * PHID + kc * 16 + ce;
        cp16(st + QK_AH + so, pAh + g);
        cp16(st + QK_AL + so, pAl + g);
        cp16(st + QK_BH + so, pBh + g);
        cp16(st + QK_BL + so, pBl + g);
    };

    auto compute_stage = [&](int stage) {
        const uint32_t st = sb + stage * QK_STAGE;
        uint32_t bh0[4], bh1[4], bl0[4], bl1[4], a[4][4];
        ldm_x4(bh0, st + QK_BH + b4_off);
        ldm_x4(bh1, st + QK_BH + b4_off + 768);
        ldm_x4(bl0, st + QK_BL + b4_off);
        ldm_x4(bl1, st + QK_BL + b4_off + 768);
#pragma unroll
        for (int mi = 0; mi < 4; mi++)
            ldm_x4(a[mi], st + QK_AH + a_off + mi * 768);
#pragma unroll
        for (int mi = 0; mi < 4; mi++) {
            mma_bf16(acc[mi][0], a[mi], bh0);
            mma_bf16(acc[mi][1], a[mi], bh0 + 2);
            mma_bf16(acc[mi][2], a[mi], bh1);
            mma_bf16(acc[mi][3], a[mi], bh1 + 2);
        }
#pragma unroll
        for (int mi = 0; mi < 4; mi++) {
            mma_bf16(acc[mi][0], a[mi], bl0);
            mma_bf16(acc[mi][1], a[mi], bl0 + 2);
            mma_bf16(acc[mi][2], a[mi], bl1);
            mma_bf16(acc[mi][3], a[mi], bl1 + 2);
        }
#pragma unroll
        for (int mi = 0; mi < 4; mi++)
            ldm_x4(a[mi], st + QK_AL + a_off + mi * 768);
#pragma unroll
        for (int mi = 0; mi < 4; mi++) {
            mma_bf16(acc[mi][0], a[mi], bh0);
            mma_bf16(acc[mi][1], a[mi], bh0 + 2);
            mma_bf16(acc[mi][2], a[mi], bh1);
            mma_bf16(acc[mi][3], a[mi], bh1 + 2);
        }
    };

    load_stage(0, 0);
    CP_COMMIT();
    load_stage(1, 1);
    CP_COMMIT();
    load_stage(2, 2);
    CP_COMMIT();
    const int NKC = PHID / 16;   // 128
    for (int kc = 0; kc < NKC; kc++) {
        if (kc < NKC - 2)      { CP_WAIT(2); }
        else if (kc == NKC - 2){ CP_WAIT(1); }
        else                   { CP_WAIT(0); }
        __syncthreads();
        compute_stage(kc & 3);
        if (kc + 3 < NKC) {
            load_stage((kc + 3) & 3, kc + 3);
            CP_COMMIT();
        }
    }

    __nv_bfloat16* Oh = sel ? Kh : Qh;
    __nv_bfloat16* Ol = sel ? Kl : Ql;
#pragma unroll
    for (int mi = 0; mi < 4; mi++) {
        const int row = m0 + wm * 64 + mi * 16 + (lane >> 2);
#pragma unroll
        for (int ni = 0; ni < 4; ni++) {
            const int col = n0 + wn * 32 + ni * 8 + (lane & 3) * 2;
            const float b0 = bias[col], b1 = bias[col + 1];
            float v00 = (acc[mi][ni][0] + b0) * scale;
            float v01 = (acc[mi][ni][1] + b1) * scale;
            float v10 = (acc[mi][ni][2] + b0) * scale;
            float v11 = (acc[mi][ni][3] + b1) * scale;
            uint32_t hp, lp;
            packsplit(v00, v01, hp, lp);
            *(uint32_t*)(Oh + (size_t)row * PHID + col) = hp;
            *(uint32_t*)(Ol + (size_t)row * PHID + col) = lp;
            packsplit(v10, v11, hp, lp);
            *(uint32_t*)(Oh + (size_t)(row + 8) * PHID + col) = hp;
            *(uint32_t*)(Ol + (size_t)(row + 8) * PHID + col) = lp;
        }
    }
}

// ---------------------------------------------------------------------------
// fp16 2-combo GEMM: C = (Ah + Al) @ B^T + bias.
// 4-stage BK=16 ring (same structure as gemm_qk), 1 barrier per chunk,
// 3-chunk prefetch.
// ---------------------------------------------------------------------------
__global__ __launch_bounds__(256, 2) void gemm_f16_2c(
    const __half* __restrict__ Ah, const __half* __restrict__ Al,
    const __half* __restrict__ Bt,
    const float* __restrict__ bias, float* __restrict__ Cf,
    __half* __restrict__ Co)
{
    extern __shared__ char smem[];
    const uint32_t sb = smem_u32(smem);
    const int tid  = threadIdx.x;
    const int lane = tid & 31;
    const int warp = tid >> 5;
    const int wm = warp >> 2;
    const int wn = warp & 3;
    const int m0 = blockIdx.y * 128;
    const int n0 = blockIdx.x * 128;

    const __half* pAh = Ah + (size_t)m0 * PHID;
    const __half* pAl = Al + (size_t)m0 * PHID;
    const __half* pB  = Bt + (size_t)n0 * PHID;

    const int r0 = tid >> 1;               // 0..127
    const int ce = (tid & 1) * 8;
    const uint32_t so = (uint32_t)(r0 * 48 + (tid & 1) * 16);

    const uint32_t a_off = (uint32_t)((wm * 64 + (lane & 15)) * 48 + ((lane >> 4) << 4));
    const uint32_t b4_off = (uint32_t)((wn * 32 + ((lane >> 4) << 3) + (lane & 7)) * 48
                                       + ((lane & 8) ? 16 : 0));

    float acc[4][4][4];
#pragma unroll
    for (int mi = 0; mi < 4; mi++)
#pragma unroll
        for (int ni = 0; ni < 4; ni++)
#pragma unroll
            for (int j = 0; j < 4; j++) acc[mi][ni][j] = 0.0f;

    auto load_stage = [&](int stage, int kc) {
        const uint32_t st = sb + stage * F2_STAGE;
        const size_t g = (size_t)r0 * PHID + kc * 16 + ce;
        cp16(st + F2_AH + so, pAh + g);
        cp16(st + F2_AL + so, pAl + g);
        cp16(st + F2_B  + so, pB + g);
    };

    auto compute_stage = [&](int stage) {
        const uint32_t st = sb + stage * F2_STAGE;
        uint32_t b0[4], b1[4], a[4][4];
        ldm_x4(b0, st + F2_B + b4_off);
        ldm_x4(b1, st + F2_B + b4_off + 768);
#pragma unroll
        for (int mi = 0; mi < 4; mi++)
            ldm_x4(a[mi], st + F2_AH + a_off + mi * 768);
#pragma unroll
        for (int mi = 0; mi < 4; mi++) {
            mma_f16(acc[mi][0], a[mi], b0);
            mma_f16(acc[mi][1], a[mi], b0 + 2);
            mma_f16(acc[mi][2], a[mi], b1);
            mma_f16(acc[mi][3], a[mi], b1 + 2);
        }
#pragma unroll
        for (int mi = 0; mi < 4; mi++)
            ldm_x4(a[mi], st + F2_AL + a_off + mi * 768);
#pragma unroll
        for (int mi = 0; mi < 4; mi++) {
            mma_f16(acc[mi][0], a[mi], b0);
            mma_f16(acc[mi][1], a[mi], b0 + 2);
            mma_f16(acc[mi][2], a[mi], b1);
            mma_f16(acc[mi][3], a[mi], b1 + 2);
        }
    };

    load_stage(0, 0);
    CP_COMMIT();
    load_stage(1, 1);
    CP_COMMIT();
    load_stage(2, 2);
    CP_COMMIT();
    const int NKC = PHID / 16;   // 128
    for (int kc = 0; kc < NKC; kc++) {
        if (kc < NKC - 2)      { CP_WAIT(2); }
        else if (kc == NKC - 2){ CP_WAIT(1); }
        else                   { CP_WAIT(0); }
        __syncthreads();
        compute_stage(kc & 3);
        if (kc + 3 < NKC) {
            load_stage((kc + 3) & 3, kc + 3);
            CP_COMMIT();
        }
    }

#pragma unroll
    for (int mi = 0; mi < 4; mi++) {
        const int row = m0 + wm * 64 + mi * 16 + (lane >> 2);
#pragma unroll
        for (int ni = 0; ni < 4; ni++) {
            const int col = n0 + wn * 32 + ni * 8 + (lane & 3) * 2;
            const float b0 = bias[col], b1 = bias[col + 1];
            float v00 = acc[mi][ni][0] + b0;
            float v01 = acc[mi][ni][1] + b1;
            float v10 = acc[mi][ni][2] + b0;
            float v11 = acc[mi][ni][3] + b1;
            if (Cf) {
                *(float2*)(Cf + (size_t)row * PHID + col)       = make_float2(v00, v01);
                *(float2*)(Cf + (size_t)(row + 8) * PHID + col) = make_float2(v10, v11);
            } else {
                __half2 p0 = __floats2half2_rn(v00, v01);
                __half2 p1 = __floats2half2_rn(v10, v11);
                *(uint32_t*)(Co + (size_t)row * PHID + col) =
                    *reinterpret_cast<uint32_t*>(&p0);
                *(uint32_t*)(Co + (size_t)(row + 8) * PHID + col) =
                    *reinterpret_cast<uint32_t*>(&p1);
            }
        }
    }
}

// ---------------------------------------------------------------------------
// Tensor-core flash attention, 2 CTAs/SM: CTA = 128 threads (4 warps),
// 64 q-rows, 32-key K/V tiles, 3-stage ring, 1 barrier per tile.
// ---------------------------------------------------------------------------
#define A2_LDB  272
#define A2_QH   0
#define A2_QL   (64 * A2_LDB)             // 17408
#define A2_ST0  (2 * 64 * A2_LDB)         // 34816
#define A2_TILE (32 * A2_LDB)             // 8704
#define A2_STAGE (3 * A2_TILE)            // 26112
#define A2_SMEM (A2_ST0 + 3 * A2_STAGE)   // 113152

__global__ __launch_bounds__(128, 2) void attn_mma(
    const __nv_bfloat16* __restrict__ Qh, const __nv_bfloat16* __restrict__ Ql,
    const __nv_bfloat16* __restrict__ Kh, const __nv_bfloat16* __restrict__ Kl,
    const __half* __restrict__ Vh,
    const float* __restrict__ Bias,
    __half* __restrict__ Ch, __half* __restrict__ Cl)
{
    extern __shared__ char smem[];
    const uint32_t sb = smem_u32(smem);
    const int tid = threadIdx.x;
    const int lane = tid & 31;
    const int warp = tid >> 5;          // 0..3
    const int bh = blockIdx.y;
    const int b  = bh >> 4;
    const int h  = bh & 15;
    const int q0 = blockIdx.x * 64;
    const float L2E = 1.44269504f;

    const size_t base = (size_t)b * PS * PHID + (size_t)h * PD;
    const __nv_bfloat16* pQh = Qh + base + (size_t)q0 * PHID;
    const __nv_bfloat16* pQl = Ql + base + (size_t)q0 * PHID;
    const __nv_bfloat16* pKh = Kh + base;
    const __nv_bfloat16* pKl = Kl + base;
    const __half* pVh = Vh + base;

    // Q loader
    {
        const int r = tid >> 1;
        const int ce = (tid & 1) * 64;
        const uint32_t so = (uint32_t)(r * A2_LDB + (tid & 1) * 128);
#pragma unroll
        for (int i = 0; i < 8; i++) {
            cp16(sb + A2_QH + so + i * 16, pQh + (size_t)r * PHID + ce + i * 8);
            cp16(sb + A2_QL + so + i * 16, pQl + (size_t)r * PHID + ce + i * 8);
        }
    }

    // K/V stage loader (3 tiles of 32 rows: Kh, Kl, Vh)
    const int kvr  = tid >> 2;
    const int kvce = (tid & 3) * 32;
    const uint32_t kvso = (uint32_t)(kvr * A2_LDB + (tid & 3) * 64);
    auto load_stage = [&](int stage, int t) {
        const uint32_t st = sb + A2_ST0 + stage * A2_STAGE;
        const size_t g = (size_t)(t * 32 + kvr) * PHID + kvce;
#pragma unroll
        for (int i = 0; i < 4; i++) {
            cp16(st + kvso + i * 16,               pKh + g + i * 8);
            cp16(st + A2_TILE + kvso + i * 16,     pKl + g + i * 8);
            cp16(st + 2 * A2_TILE + kvso + i * 16, pVh + g + i * 8);
        }
    };

    load_stage(0, 0);
    CP_COMMIT();
    load_stage(1, 1);
    CP_COMMIT();

    const uint32_t q_off = (uint32_t)((warp * 16 + (lane & 15)) * A2_LDB + ((lane >> 4) << 4));
    const uint32_t k4_off = (uint32_t)((((lane >> 4) << 3) + (lane & 7)) * A2_LDB
                                       + ((lane & 8) ? 16 : 0));
    const uint32_t v4_off = (uint32_t)((((lane >> 3) & 1) * 8 + (lane & 7)) * A2_LDB
                                       + (lane >> 4) * 16);

    const float* biasR0 = Bias + ((size_t)bh * PS + q0 + warp * 16 + (lane >> 2)) * PS;
    const float* biasR1 = biasR0 + 8 * PS;
    const int bcol = (lane & 3) * 2;

    float o[16][4];
#pragma unroll
    for (int nd = 0; nd < 16; nd++)
#pragma unroll
        for (int j = 0; j < 4; j++) o[nd][j] = 0.0f;
    float lacc[4] = {0.0f, 0.0f, 0.0f, 0.0f};
    float m0 = -1e30f, m1 = -1e30f;
    const uint32_t ONESB[2] = {0x3C003C00u, 0x3C003C00u};

    float2 nb0[4], nb1[4];
#pragma unroll
    for (int nf = 0; nf < 4; nf++) {
        nb0[nf] = *(const float2*)(biasR0 + nf * 8 + bcol);
        nb1[nf] = *(const float2*)(biasR1 + nf * 8 + bcol);
    }

    const int NT = PS / 32;   // 64 tiles
    for (int t = 0; t < NT; t++) {
        if (t < NT - 1) { CP_WAIT(1); } else { CP_WAIT(0); }
        __syncthreads();

        const uint32_t st = sb + A2_ST0 + (t % 3) * A2_STAGE;

        float sc[4][4];
#pragma unroll
        for (int nf = 0; nf < 4; nf++) {
            sc[nf][0] = nb0[nf].x; sc[nf][1] = nb0[nf].y;
            sc[nf][2] = nb1[nf].x; sc[nf][3] = nb1[nf].y;
        }
        if (t + 1 < NT) {
            const int k1 = (t + 1) * 32;
#pragma unroll
            for (int nf = 0; nf < 4; nf++) {
                nb0[nf] = *(const float2*)(biasR0 + k1 + nf * 8 + bcol);
                nb1[nf] = *(const float2*)(biasR1 + k1 + nf * 8 + bcol);
            }
        }

        // ---- scores += Q K^T (split 3-combo), K via x4 pairs ----
#pragma unroll
        for (int ks = 0; ks < 8; ks++) {
            uint32_t qa[4], qla[4];
            ldm_x4(qa,  sb + A2_QH + q_off + ks * 32);
            ldm_x4(qla, sb + A2_QL + q_off + ks * 32);
#pragma unroll
            for (int nf2 = 0; nf2 < 2; nf2++) {
                uint32_t kbh[4], kbl[4];
                ldm_x4(kbh, st + k4_off + nf2 * 16 * A2_LDB + ks * 32);
                ldm_x4(kbl, st + A2_TILE + k4_off + nf2 * 16 * A2_LDB + ks * 32);
                mma_bf16(sc[2*nf2],   qa,  kbh);
                mma_bf16(sc[2*nf2+1], qa,  kbh + 2);
                mma_bf16(sc[2*nf2],   qa,  kbl);
                mma_bf16(sc[2*nf2+1], qa,  kbl + 2);
                mma_bf16(sc[2*nf2],   qla, kbh);
                mma_bf16(sc[2*nf2+1], qla, kbh + 2);
            }
        }

        // ---- online softmax: max ----
        float mx0 = sc[0][0], mx1 = sc[0][2];
#pragma unroll
        for (int nf = 0; nf < 4; nf++) {
            mx0 = fmaxf(mx0, fmaxf(sc[nf][0], sc[nf][1]));
            mx1 = fmaxf(mx1, fmaxf(sc[nf][2], sc[nf][3]));
        }
        mx0 = fmaxf(mx0, __shfl_xor_sync(0xffffffffu, mx0, 1));
        mx0 = fmaxf(mx0, __shfl_xor_sync(0xffffffffu, mx0, 2));
        mx1 = fmaxf(mx1, __shfl_xor_sync(0xffffffffu, mx1, 1));
        mx1 = fmaxf(mx1, __shfl_xor_sync(0xffffffffu, mx1, 2));
        const float mn0 = fmaxf(m0, mx0), mn1 = fmaxf(m1, mx1);
        const float mL0 = mn0 * L2E, mL1 = mn1 * L2E;
        const float al0 = ex2f((m0 - mn0) * L2E);
        const float al1 = ex2f((m1 - mn1) * L2E);
        m0 = mn0; m1 = mn1;

        if (al0 != 1.0f || al1 != 1.0f) {
#pragma unroll
            for (int nd = 0; nd < 16; nd++) {
                o[nd][0] *= al0; o[nd][1] *= al0;
                o[nd][2] *= al1; o[nd][3] *= al1;
            }
            lacc[0] *= al0; lacc[1] *= al0;
            lacc[2] *= al1; lacc[3] *= al1;
        }

        // ---- PV: P exp/pack per 16-key group, then its MMAs ----
#pragma unroll
        for (int j2 = 0; j2 < 2; j2++) {
            const int f0 = 2 * j2, f1 = f0 + 1;
            uint32_t pf[4];
            pf[0] = h2ex2(fmaf(sc[f0][0], L2E, -mL0), fmaf(sc[f0][1], L2E, -mL0));
            pf[1] = h2ex2(fmaf(sc[f0][2], L2E, -mL1), fmaf(sc[f0][3], L2E, -mL1));
            pf[2] = h2ex2(fmaf(sc[f1][0], L2E, -mL0), fmaf(sc[f1][1], L2E, -mL0));
            pf[3] = h2ex2(fmaf(sc[f1][2], L2E, -mL1), fmaf(sc[f1][3], L2E, -mL1));
            mma_f16(lacc, pf, ONESB);
            const uint32_t vrow = st + 2 * A2_TILE + v4_off + j2 * 16 * A2_LDB;
#pragma unroll
            for (int nd2 = 0; nd2 < 8; nd2++) {
                uint32_t vbh[4];
                ldm_x4t(vbh, vrow + nd2 * 32);
                mma_f16(o[2*nd2],   pf, vbh);
                mma_f16(o[2*nd2+1], pf, vbh + 2);
            }
        }

        if (t + 2 < NT) {
            load_stage((t + 2) % 3, t + 2);
            CP_COMMIT();
        }
    }

    // ---- epilogue: normalize, split fp16, store ctx ----
    const float inv0 = 1.0f / lacc[0], inv1 = 1.0f / lacc[2];
    const int rg0 = q0 + warp * 16 + (lane >> 2);
    __half* och = Ch + base;
    __half* ocl = Cl + base;
#pragma unroll
    for (int nd = 0; nd < 16; nd++) {
        const int col = nd * 8 + (lane & 3) * 2;
        uint32_t hp, lp;
        packsplit_f16(o[nd][0] * inv0, o[nd][1] * inv0, hp, lp);
        *(uint32_t*)(och + (size_t)rg0 * PHID + col) = hp;
        *(uint32_t*)(ocl + (size_t)rg0 * PHID + col) = lp;
        packsplit_f16(o[nd][2] * inv1, o[nd][3] * inv1, hp, lp);
        *(uint32_t*)(och + (size_t)(rg0 + 8) * PHID + col) = hp;
        *(uint32_t*)(ocl + (size_t)(rg0 + 8) * PHID + col) = lp;
    }
}

// ---------------------------------------------------------------------------
extern "C" void kernel_launch(void* const* d_in, const int* in_sizes, int n_in,
                              void* d_out, int out_size)
{
    (void)in_sizes; (void)n_in; (void)out_size;
    const float* x    = (const float*)d_in[0];
    const float* bias = (const float*)d_in[1];
    const float* Wq   = (const float*)d_in[2];
    const float* bq   = (const float*)d_in[3];
    const float* Wk   = (const float*)d_in[4];
    const float* bk   = (const float*)d_in[5];
    const float* Wv   = (const float*)d_in[6];
    const float* bv   = (const float*)d_in[7];
    const float* Wo   = (const float*)d_in[8];
    const float* bo   = (const float*)d_in[9];
    float* out = (float*)d_out;

    __nv_bfloat16 *xh, *xl, *qh, *ql, *kh, *kl;
    __half *xh2, *xl2, *vhf, *ch2, *cl2, *wvt, *wot;
    __nv_bfloat16 *wqh, *wql, *wkh, *wkl;
    cudaGetSymbolAddress((void**)&xh, g_xh);
    cudaGetSymbolAddress((void**)&xl, g_xl);
    cudaGetSymbolAddress((void**)&xh2, g_xh2);
    cudaGetSymbolAddress((void**)&xl2, g_xl2);
    cudaGetSymbolAddress((void**)&qh, g_qh);
    cudaGetSymbolAddress((void**)&ql, g_ql);
    cudaGetSymbolAddress((void**)&kh, g_kh);
    cudaGetSymbolAddress((void**)&kl, g_kl);
    cudaGetSymbolAddress((void**)&vhf, g_vhf);
    cudaGetSymbolAddress((void**)&ch2, g_ch2);
    cudaGetSymbolAddress((void**)&cl2, g_cl2);
    cudaGetSymbolAddress((void**)&wqh, g_wqh);
    cudaGetSymbolAddress((void**)&wql, g_wql);
    cudaGetSymbolAddress((void**)&wkh, g_wkh);
    cudaGetSymbolAddress((void**)&wkl, g_wkl);
    cudaGetSymbolAddress((void**)&wvt, g_wvt);
    cudaGetSymbolAddress((void**)&wot, g_wot);

    static bool attr_set = false;
    if (!attr_set) {
        cudaFuncSetAttribute(gemm_qk,
                             cudaFuncAttributeMaxDynamicSharedMemorySize, QK_SMEM);
        cudaFuncSetAttribute(gemm_f16_2c,
                             cudaFuncAttributeMaxDynamicSharedMemorySize, F2_SMEM);
        cudaFuncSetAttribute(attn_mma,
                             cudaFuncAttributeMaxDynamicSharedMemorySize, A2_SMEM);
        attr_set = true;
    }

    // 1) conversions
    {
        int n4 = PM * PHID / 4;
        split_x_kernel<<<(n4 + 255) / 256, 256>>>(x, xh, xl, xh2, xl2, n4);
        dim3 tg(PHID / 32, PHID / 32, 4);
        dim3 tb(32, 8);
        transpose_all_kernel<<<tg, tb>>>(Wq, Wk, Wv, Wo,
                                         wqh, wql, wkh, wkl, wvt, wot);
    }

    // 2) projections
    dim3 qkgrid(2 * PHID / 128, PM / 128);    // (32, 32)
    gemm_qk<<<qkgrid, 256, QK_SMEM>>>(xh, xl, wqh, wql, wkh, wkl,
                                      bq, bk, qh, ql, kh, kl);
    dim3 vgrid(PHID / 128, PM / 128);         // (16, 32)
    gemm_f16_2c<<<vgrid, 256, F2_SMEM>>>(xh2, xl2, wvt, bv, nullptr, vhf);

    // 3) tensor-core attention (2 CTAs/SM) -> split fp16 ctx
    dim3 agrid(PS / 64, PB * PH);             // (32, 32)
    attn_mma<<<agrid, 128, A2_SMEM>>>(qh, ql, kh, kl, vhf, bias, ch2, cl2);

    // 4) output projection -> fp32 out
    gemm_f16_2c<<<vgrid, 256, F2_SMEM>>>(ch2, cl2, wot, bo, out, nullptr);
}

// round 16
// speedup vs baseline: 1.0722x; 1.0722x over previous
#include <cuda_runtime.h>
#include <cuda_bf16.h>
#include <cuda_fp16.h>
#include <math.h>
#include <stdint.h>

// Problem constants
#define PB   2
#define PS   2048
#define PHID 2048
#define PH   16
#define PD   128
#define PM   (PB * PS)          // 4096 rows
#define QSCALE 11.313708498984760f   // sqrt(128)

// ---------------------------------------------------------------------------
// Scratch (no cudaMalloc allowed)
// ---------------------------------------------------------------------------
__device__ __nv_bfloat16 g_xh[(size_t)PM * PHID];    // x split bf16 (QK path)
__device__ __nv_bfloat16 g_xl[(size_t)PM * PHID];
__device__ __half        g_xh2[(size_t)PM * PHID];   // x split fp16 (V path)
__device__ __half        g_xl2[(size_t)PM * PHID];
__device__ __nv_bfloat16 g_qh[(size_t)PM * PHID];
__device__ __nv_bfloat16 g_ql[(size_t)PM * PHID];
__device__ __nv_bfloat16 g_kh[(size_t)PM * PHID];
__device__ __nv_bfloat16 g_kl[(size_t)PM * PHID];
__device__ __half        g_vhf[(size_t)PM * PHID];   // V, fp16
__device__ __half        g_ch2[(size_t)PM * PHID];   // ctx split fp16
__device__ __half        g_cl2[(size_t)PM * PHID];

// transposed weights [N,K]
__device__ __nv_bfloat16 g_wqh[(size_t)PHID * PHID];
__device__ __nv_bfloat16 g_wql[(size_t)PHID * PHID];
__device__ __nv_bfloat16 g_wkh[(size_t)PHID * PHID];
__device__ __nv_bfloat16 g_wkl[(size_t)PHID * PHID];
__device__ __half        g_wvt[(size_t)PHID * PHID]; // Wv^T single fp16
__device__ __half        g_wot[(size_t)PHID * PHID]; // Wo^T single fp16

// ---------------------------------------------------------------------------
// Helpers
// ---------------------------------------------------------------------------
__device__ __forceinline__ uint32_t smem_u32(const void* p) {
    uint32_t a;
    asm("{ .reg .u64 t; cvta.to.shared.u64 t, %1; cvt.u32.u64 %0, t; }"
        : "=r"(a) : "l"(p));
    return a;
}

__device__ __forceinline__ void cp16(uint32_t s, const void* g) {
    asm volatile("cp.async.cg.shared.global [%0], [%1], 16;" :: "r"(s), "l"(g));
}
#define CP_COMMIT() asm volatile("cp.async.commit_group;" ::: "memory")
#define CP_WAIT(n)  asm volatile("cp.async.wait_group %0;" :: "n"(n) : "memory")

__device__ __forceinline__ void ldm_x4(uint32_t* r, uint32_t addr) {
    asm volatile("ldmatrix.sync.aligned.m8n8.x4.shared.b16 {%0,%1,%2,%3}, [%4];"
                 : "=r"(r[0]), "=r"(r[1]), "=r"(r[2]), "=r"(r[3]) : "r"(addr));
}
__device__ __forceinline__ void ldm_x4t(uint32_t* r, uint32_t addr) {
    asm volatile("ldmatrix.sync.aligned.m8n8.x4.trans.shared.b16 {%0,%1,%2,%3}, [%4];"
                 : "=r"(r[0]), "=r"(r[1]), "=r"(r[2]), "=r"(r[3]) : "r"(addr));
}
__device__ __forceinline__ void mma_bf16(float* c, const uint32_t* a, const uint32_t* b) {
    asm volatile(
        "mma.sync.aligned.m16n8k16.row.col.f32.bf16.bf16.f32 "
        "{%0,%1,%2,%3}, {%4,%5,%6,%7}, {%8,%9}, {%0,%1,%2,%3};"
        : "+f"(c[0]), "+f"(c[1]), "+f"(c[2]), "+f"(c[3])
        : "r"(a[0]), "r"(a[1]), "r"(a[2]), "r"(a[3]), "r"(b[0]), "r"(b[1]));
}
__device__ __forceinline__ void mma_f16(float* c, const uint32_t* a, const uint32_t* b) {
    asm volatile(
        "mma.sync.aligned.m16n8k16.row.col.f32.f16.f16.f32 "
        "{%0,%1,%2,%3}, {%4,%5,%6,%7}, {%8,%9}, {%0,%1,%2,%3};"
        : "+f"(c[0]), "+f"(c[1]), "+f"(c[2]), "+f"(c[3])
        : "r"(a[0]), "r"(a[1]), "r"(a[2]), "r"(a[3]), "r"(b[0]), "r"(b[1]));
}

__device__ __forceinline__ float ex2f(float x) {
    float r;
    asm("ex2.approx.f32 %0, %1;" : "=f"(r) : "f"(x));
    return r;
}

// pack two fp32 exponent args into f16x2 and take 2^x on both at once
__device__ __forceinline__ uint32_t h2ex2(float y0, float y1) {
    uint32_t h, p;
    asm("cvt.rn.f16x2.f32 %0, %1, %2;" : "=r"(h) : "f"(y1), "f"(y0));
    asm("ex2.approx.f16x2 %0, %1;" : "=r"(p) : "r"(h));
    return p;
}

// Fast RNE split of two floats into (hi bf16x2, lo bf16x2).
__device__ __forceinline__ void packsplit(float a, float b, uint32_t& hp, uint32_t& lp) {
    asm("cvt.rn.bf16x2.f32 %0, %1, %2;" : "=r"(hp) : "f"(b), "f"(a));
    float ah = __uint_as_float(hp << 16);
    float bh = __uint_as_float(hp & 0xFFFF0000u);
    float la = a - ah;
    float lb = b - bh;
    asm("cvt.rn.bf16x2.f32 %0, %1, %2;" : "=r"(lp) : "f"(lb), "f"(la));
}

// RNE split of two floats into (hi f16x2, lo f16x2).
__device__ __forceinline__ void packsplit_f16(float a, float b, uint32_t& hp, uint32_t& lp) {
    __half2 h = __floats2half2_rn(a, b);
    float la = a - __half2float(__low2half(h));
    float lb = b - __half2float(__high2half(h));
    __half2 l = __floats2half2_rn(la, lb);
    hp = *reinterpret_cast<uint32_t*>(&h);
    lp = *reinterpret_cast<uint32_t*>(&l);
}

// ---------------------------------------------------------------------------
// Conversion kernels
// ---------------------------------------------------------------------------
__global__ void split_x_kernel(const float* __restrict__ in,
                               __nv_bfloat16* __restrict__ hb,
                               __nv_bfloat16* __restrict__ lb,
                               __half* __restrict__ hf,
                               __half* __restrict__ lf, int n4)
{
    int i = blockIdx.x * blockDim.x + threadIdx.x;
    if (i >= n4) return;
    float4 v = ((const float4*)in)[i];
    uint32_t h0, l0, h1, l1;
    packsplit(v.x, v.y, h0, l0);
    packsplit(v.z, v.w, h1, l1);
    ((uint32_t*)hb)[2*i]   = h0;
    ((uint32_t*)hb)[2*i+1] = h1;
    ((uint32_t*)lb)[2*i]   = l0;
    ((uint32_t*)lb)[2*i+1] = l1;
    packsplit_f16(v.x, v.y, h0, l0);
    packsplit_f16(v.z, v.w, h1, l1);
    ((uint32_t*)hf)[2*i]   = h0;
    ((uint32_t*)hf)[2*i+1] = h1;
    ((uint32_t*)lf)[2*i]   = l0;
    ((uint32_t*)lf)[2*i+1] = l1;
}

// One launch transposes all 4 weight matrices.  z=0,1 -> bf16 split (Wq, Wk);
// z=2,3 -> single fp16 (Wv, Wo).
__global__ void transpose_all_kernel(
    const float* __restrict__ Wq, const float* __restrict__ Wk,
    const float* __restrict__ Wv, const float* __restrict__ Wo,
    __nv_bfloat16* __restrict__ Tqh, __nv_bfloat16* __restrict__ Tql,
    __nv_bfloat16* __restrict__ Tkh, __nv_bfloat16* __restrict__ Tkl,
    __half* __restrict__ Tv, __half* __restrict__ To)
{
    __shared__ float t[32][33];
    int z = blockIdx.z;
    const float* W = (z == 0) ? Wq : (z == 1) ? Wk : (z == 2) ? Wv : Wo;
    int n0 = blockIdx.x * 32, k0 = blockIdx.y * 32;
    int tx = threadIdx.x, ty0 = threadIdx.y;   // 32 x 8
#pragma unroll
    for (int j = 0; j < 32; j += 8)
        t[ty0 + j][tx] = W[(size_t)(k0 + ty0 + j) * PHID + n0 + tx];
    __syncthreads();
#pragma unroll
    for (int j = 0; j < 32; j += 8) {
        int n = ty0 + j;
        float v = t[tx][n];
        size_t o = (size_t)(n0 + n) * PHID + k0 + tx;
        if (z < 2) {
            __nv_bfloat16 h = __float2bfloat16(v);
            __nv_bfloat16 l = __float2bfloat16(v - __bfloat162float(h));
            if (z == 0) { Tqh[o] = h; Tql[o] = l; }
            else        { Tkh[o] = h; Tkl[o] = l; }
        } else {
            __half h = __float2half_rn(v);
            if (z == 2) Tv[o] = h; else To[o] = h;
        }
    }
}

// ---------------------------------------------------------------------------
// GEMM tile configs
// ---------------------------------------------------------------------------
// gemm_qk 4-stage BK=16 ring: tile = 128 rows x 48B (16 bf16 + 8 pad)
#define QK_TILE  6144
#define QK_AH    0
#define QK_AL    (QK_TILE)
#define QK_BH    (2 * QK_TILE)
#define QK_BL    (3 * QK_TILE)
#define QK_STAGE (4 * QK_TILE)   // 24576
#define QK_SMEM  (4 * QK_STAGE)  // 98304

// gemm_f16_2c: BK=32 tiles of 128 x 80B, 3-stage pipeline (R14 config)
#define LDT   40
#define TILE_B (128 * LDT * 2)   // 10240
#define OFF_AH 0
#define OFF_AL (TILE_B)
#define OFF_BH (2 * TILE_B)
#define STAGE2_B (3 * TILE_B)    // 30720
#define GSMEM2 (3 * STAGE2_B)    // 92160

// ---------------------------------------------------------------------------
// Q/K projection GEMM (split-bf16, 3 combos): sel = blockIdx.x>>4 in {0,1}.
// 4-stage BK=16 ring, ONE __syncthreads per chunk, 3-chunk prefetch.
// ---------------------------------------------------------------------------
__global__ __launch_bounds__(256, 2) void gemm_qk(
    const __nv_bfloat16* __restrict__ Ah, const __nv_bfloat16* __restrict__ Al,
    const __nv_bfloat16* __restrict__ Wqh, const __nv_bfloat16* __restrict__ Wql,
    const __nv_bfloat16* __restrict__ Wkh, const __nv_bfloat16* __restrict__ Wkl,
    const float* __restrict__ bq, const float* __restrict__ bk,
    __nv_bfloat16* __restrict__ Qh, __nv_bfloat16* __restrict__ Ql,
    __nv_bfloat16* __restrict__ Kh, __nv_bfloat16* __restrict__ Kl)
{
    extern __shared__ char smem[];
    const uint32_t sb = smem_u32(smem);
    const int tid  = threadIdx.x;
    const int lane = tid & 31;
    const int warp = tid >> 5;
    const int wm = warp >> 2;
    const int wn = warp & 3;
    const int sel = blockIdx.x >> 4;            // 0=Q 1=K
    const int n0  = (blockIdx.x & 15) * 128;
    const int m0  = blockIdx.y * 128;

    const __nv_bfloat16* Bh = sel ? Wkh : Wqh;
    const __nv_bfloat16* Bl = sel ? Wkl : Wql;
    const float* bias = sel ? bk : bq;
    const float scale = sel ? 1.0f : QSCALE;

    const __nv_bfloat16* pAh = Ah + (size_t)m0 * PHID;
    const __nv_bfloat16* pAl = Al + (size_t)m0 * PHID;
    const __nv_bfloat16* pBh = Bh + (size_t)n0 * PHID;
    const __nv_bfloat16* pBl = Bl + (size_t)n0 * PHID;

    const int r0 = tid >> 1;               // 0..127
    const int ce = (tid & 1) * 8;
    const uint32_t so = (uint32_t)(r0 * 48 + (tid & 1) * 16);

    const uint32_t a_off = (uint32_t)((wm * 64 + (lane & 15)) * 48 + ((lane >> 4) << 4));
    const uint32_t b4_off = (uint32_t)((wn * 32 + ((lane >> 4) << 3) + (lane & 7)) * 48
                                       + ((lane & 8) ? 16 : 0));

    float acc[4][4][4];
#pragma unroll
    for (int mi = 0; mi < 4; mi++)
#pragma unroll
        for (int ni = 0; ni < 4; ni++)
#pragma unroll
            for (int j = 0; j < 4; j++) acc[mi][ni][j] = 0.0f;

    auto load_stage = [&](int stage, int kc) {
        const uint32_t st = sb + stage * QK_STAGE;
        const size_t g = (size_t)r0 * PHID + kc * 16 + ce;
        cp16(st + QK_AH + so, pAh + g);
        cp16(st + QK_AL + so, pAl + g);
        cp16(st + QK_BH + so, pBh + g);
        cp16(st + QK_BL + so, pBl + g);
    };

    auto compute_stage = [&](int stage) {
        const uint32_t st = sb + stage * QK_STAGE;
        uint32_t bh0[4], bh1[4], bl0[4], bl1[4], a[4][4];
        ldm_x4(bh0, st + QK_BH + b4_off);
        ldm_x4(bh1, st + QK_BH + b4_off + 768);
        ldm_x4(bl0, st + QK_BL + b4_off);
        ldm_x4(bl1, st + QK_BL + b4_off + 768);
#pragma unroll
        for (int mi = 0; mi < 4; mi++)
            ldm_x4(a[mi], st + QK_AH + a_off + mi * 768);
#pragma unroll
        for (int mi = 0; mi < 4; mi++) {
            mma_bf16(acc[mi][0], a[mi], bh0);
            mma_bf16(acc[mi][1], a[mi], bh0 + 2);
            mma_bf16(acc[mi][2], a[mi], bh1);
            mma_bf16(acc[mi][3], a[mi], bh1 + 2);
        }
#pragma unroll
        for (int mi = 0; mi < 4; mi++) {
            mma_bf16(acc[mi][0], a[mi], bl0);
            mma_bf16(acc[mi][1], a[mi], bl0 + 2);
            mma_bf16(acc[mi][2], a[mi], bl1);
            mma_bf16(acc[mi][3], a[mi], bl1 + 2);
        }
#pragma unroll
        for (int mi = 0; mi < 4; mi++)
            ldm_x4(a[mi], st + QK_AL + a_off + mi * 768);
#pragma unroll
        for (int mi = 0; mi < 4; mi++) {
            mma_bf16(acc[mi][0], a[mi], bh0);
            mma_bf16(acc[mi][1], a[mi], bh0 + 2);
            mma_bf16(acc[mi][2], a[mi], bh1);
            mma_bf16(acc[mi][3], a[mi], bh1 + 2);
        }
    };

    load_stage(0, 0);
    CP_COMMIT();
    load_stage(1, 1);
    CP_COMMIT();
    load_stage(2, 2);
    CP_COMMIT();
    const int NKC = PHID / 16;   // 128
    for (int kc = 0; kc < NKC; kc++) {
        if (kc < NKC - 2)      { CP_WAIT(2); }
        else if (kc == NKC - 2){ CP_WAIT(1); }
        else                   { CP_WAIT(0); }
        __syncthreads();
        compute_stage(kc & 3);
        if (kc + 3 < NKC) {
            load_stage((kc + 3) & 3, kc + 3);
            CP_COMMIT();
        }
    }

    __nv_bfloat16* Oh = sel ? Kh : Qh;
    __nv_bfloat16* Ol = sel ? Kl : Ql;
#pragma unroll
    for (int mi = 0; mi < 4; mi++) {
        const int row = m0 + wm * 64 + mi * 16 + (lane >> 2);
#pragma unroll
        for (int ni = 0; ni < 4; ni++) {
            const int col = n0 + wn * 32 + ni * 8 + (lane & 3) * 2;
            const float b0 = bias[col], b1 = bias[col + 1];
            float v00 = (acc[mi][ni][0] + b0) * scale;
            float v01 = (acc[mi][ni][1] + b1) * scale;
            float v10 = (acc[mi][ni][2] + b0) * scale;
            float v11 = (acc[mi][ni][3] + b1) * scale;
            uint32_t hp, lp;
            packsplit(v00, v01, hp, lp);
            *(uint32_t*)(Oh + (size_t)row * PHID + col) = hp;
            *(uint32_t*)(Ol + (size_t)row * PHID + col) = lp;
            packsplit(v10, v11, hp, lp);
            *(uint32_t*)(Oh + (size_t)(row + 8) * PHID + col) = hp;
            *(uint32_t*)(Ol + (size_t)(row + 8) * PHID + col) = lp;
        }
    }
}

// ---------------------------------------------------------------------------
// fp16 2-combo GEMM: C = (Ah + Al) @ B^T + bias.  BK=32, 3-stage pipeline,
// ONE __syncthreads per K-chunk (reverted to R14 config: best measured).
// ---------------------------------------------------------------------------
__global__ __launch_bounds__(256, 2) void gemm_f16_2c(
    const __half* __restrict__ Ah, const __half* __restrict__ Al,
    const __half* __restrict__ Bt,
    const float* __restrict__ bias, float* __restrict__ Cf,
    __half* __restrict__ Co)
{
    extern __shared__ char smem[];
    const uint32_t sb = smem_u32(smem);
    const int tid  = threadIdx.x;
    const int lane = tid & 31;
    const int warp = tid >> 5;
    const int wm = warp >> 2;
    const int wn = warp & 3;
    const int m0 = blockIdx.y * 128;
    const int n0 = blockIdx.x * 128;

    const __half* pAh = Ah + (size_t)m0 * PHID;
    const __half* pAl = Al + (size_t)m0 * PHID;
    const __half* pB  = Bt + (size_t)n0 * PHID;

    const int r0 = tid >> 2;
    const int c0 = (tid & 3) * 8;
    const uint32_t so0 = (uint32_t)(r0 * 80 + (tid & 3) * 16);
    const uint32_t so1 = (uint32_t)((r0 + 64) * 80 + (tid & 3) * 16);

    const uint32_t a_off = (uint32_t)((wm * 64 + (lane & 15)) * 80 + ((lane >> 4) << 4));
    const uint32_t b4_off = (uint32_t)((wn * 32 + ((lane >> 4) << 3) + (lane & 7)) * 80
                                       + ((lane & 8) ? 16 : 0));

    float acc[4][4][4];
#pragma unroll
    for (int mi = 0; mi < 4; mi++)
#pragma unroll
        for (int ni = 0; ni < 4; ni++)
#pragma unroll
            for (int j = 0; j < 4; j++) acc[mi][ni][j] = 0.0f;

    auto load_stage = [&](int stage, int kc) {
        const uint32_t st = sb + stage * STAGE2_B;
        const size_t g0 = (size_t)r0 * PHID + kc * 32 + c0;
        const size_t g1 = (size_t)(r0 + 64) * PHID + kc * 32 + c0;
        cp16(st + OFF_AH + so0, pAh + g0);
        cp16(st + OFF_AH + so1, pAh + g1);
        cp16(st + OFF_AL + so0, pAl + g0);
        cp16(st + OFF_AL + so1, pAl + g1);
        cp16(st + OFF_BH + so0, pB + g0);
        cp16(st + OFF_BH + so1, pB + g1);
    };

    auto compute_stage = [&](int stage) {
        const uint32_t st = sb + stage * STAGE2_B;
#pragma unroll
        for (int ks = 0; ks < 2; ks++) {
            const uint32_t k32 = ks * 32;
            uint32_t bf[4][2], a[4][4];
            ldm_x4(&bf[0][0], st + OFF_BH + b4_off + k32);
            ldm_x4(&bf[2][0], st + OFF_BH + b4_off + 1280 + k32);
#pragma unroll
            for (int mi = 0; mi < 4; mi++)
                ldm_x4(a[mi], st + OFF_AH + a_off + mi * 1280 + k32);
#pragma unroll
            for (int mi = 0; mi < 4; mi++)
#pragma unroll
                for (int ni = 0; ni < 4; ni++)
                    mma_f16(acc[mi][ni], a[mi], bf[ni]);
#pragma unroll
            for (int mi = 0; mi < 4; mi++)
                ldm_x4(a[mi], st + OFF_AL + a_off + mi * 1280 + k32);
#pragma unroll
            for (int mi = 0; mi < 4; mi++)
#pragma unroll
                for (int ni = 0; ni < 4; ni++)
                    mma_f16(acc[mi][ni], a[mi], bf[ni]);
        }
    };

    load_stage(0, 0);
    CP_COMMIT();
    load_stage(1, 1);
    CP_COMMIT();
    const int NKC = PHID / 32;   // 64
    for (int kc = 0; kc < NKC; kc++) {
        if (kc < NKC - 1) { CP_WAIT(1); } else { CP_WAIT(0); }
        __syncthreads();
        compute_stage(kc % 3);
        if (kc + 2 < NKC) {
            load_stage((kc + 2) % 3, kc + 2);
            CP_COMMIT();
        }
    }

#pragma unroll
    for (int mi = 0; mi < 4; mi++) {
        const int row = m0 + wm * 64 + mi * 16 + (lane >> 2);
#pragma unroll
        for (int ni = 0; ni < 4; ni++) {
            const int col = n0 + wn * 32 + ni * 8 + (lane & 3) * 2;
            const float b0 = bias[col], b1 = bias[col + 1];
            float v00 = acc[mi][ni][0] + b0;
            float v01 = acc[mi][ni][1] + b1;
            float v10 = acc[mi][ni][2] + b0;
            float v11 = acc[mi][ni][3] + b1;
            if (Cf) {
                *(float2*)(Cf + (size_t)row * PHID + col)       = make_float2(v00, v01);
                *(float2*)(Cf + (size_t)(row + 8) * PHID + col) = make_float2(v10, v11);
            } else {
                __half2 p0 = __floats2half2_rn(v00, v01);
                __half2 p1 = __floats2half2_rn(v10, v11);
                *(uint32_t*)(Co + (size_t)row * PHID + col) =
                    *reinterpret_cast<uint32_t*>(&p0);
                *(uint32_t*)(Co + (size_t)(row + 8) * PHID + col) =
                    *reinterpret_cast<uint32_t*>(&p1);
            }
        }
    }
}

// ---------------------------------------------------------------------------
// Tensor-core flash attention, 2 CTAs/SM, Q held in REGISTERS (loop-invariant).
// CTA = 128 threads (4 warps), 64 q-rows, 32-key K/V tiles, 3-stage ring.
// ---------------------------------------------------------------------------
#define A2_LDB  272
#define A2_QH   0
#define A2_QL   (64 * A2_LDB)             // 17408
#define A2_ST0  (2 * 64 * A2_LDB)         // 34816
#define A2_TILE (32 * A2_LDB)             // 8704
#define A2_STAGE (3 * A2_TILE)            // 26112
#define A2_SMEM (A2_ST0 + 3 * A2_STAGE)   // 113152

__global__ __launch_bounds__(128, 2) void attn_mma(
    const __nv_bfloat16* __restrict__ Qh, const __nv_bfloat16* __restrict__ Ql,
    const __nv_bfloat16* __restrict__ Kh, const __nv_bfloat16* __restrict__ Kl,
    const __half* __restrict__ Vh,
    const float* __restrict__ Bias,
    __half* __restrict__ Ch, __half* __restrict__ Cl)
{
    extern __shared__ char smem[];
    const uint32_t sb = smem_u32(smem);
    const int tid = threadIdx.x;
    const int lane = tid & 31;
    const int warp = tid >> 5;          // 0..3
    const int bh = blockIdx.y;
    const int b  = bh >> 4;
    const int h  = bh & 15;
    const int q0 = blockIdx.x * 64;
    const float L2E = 1.44269504f;

    const size_t base = (size_t)b * PS * PHID + (size_t)h * PD;
    const __nv_bfloat16* pQh = Qh + base + (size_t)q0 * PHID;
    const __nv_bfloat16* pQl = Ql + base + (size_t)q0 * PHID;
    const __nv_bfloat16* pKh = Kh + base;
    const __nv_bfloat16* pKl = Kl + base;
    const __half* pVh = Vh + base;

    // Q loader (into smem; consumed once into registers below)
    {
        const int r = tid >> 1;
        const int ce = (tid & 1) * 64;
        const uint32_t so = (uint32_t)(r * A2_LDB + (tid & 1) * 128);
#pragma unroll
        for (int i = 0; i < 8; i++) {
            cp16(sb + A2_QH + so + i * 16, pQh + (size_t)r * PHID + ce + i * 8);
            cp16(sb + A2_QL + so + i * 16, pQl + (size_t)r * PHID + ce + i * 8);
        }
    }
    CP_COMMIT();

    // K/V stage loader (3 tiles of 32 rows: Kh, Kl, Vh)
    const int kvr  = tid >> 2;
    const int kvce = (tid & 3) * 32;
    const uint32_t kvso = (uint32_t)(kvr * A2_LDB + (tid & 3) * 64);
    auto load_stage = [&](int stage, int t) {
        const uint32_t st = sb + A2_ST0 + stage * A2_STAGE;
        const size_t g = (size_t)(t * 32 + kvr) * PHID + kvce;
#pragma unroll
        for (int i = 0; i < 4; i++) {
            cp16(st + kvso + i * 16,               pKh + g + i * 8);
            cp16(st + A2_TILE + kvso + i * 16,     pKl + g + i * 8);
            cp16(st + 2 * A2_TILE + kvso + i * 16, pVh + g + i * 8);
        }
    };

    load_stage(0, 0);
    CP_COMMIT();
    load_stage(1, 1);
    CP_COMMIT();

    const uint32_t q_off = (uint32_t)((warp * 16 + (lane & 15)) * A2_LDB + ((lane >> 4) << 4));
    const uint32_t k4_off = (uint32_t)((((lane >> 4) << 3) + (lane & 7)) * A2_LDB
                                       + ((lane & 8) ? 16 : 0));
    const uint32_t v4_off = (uint32_t)((((lane >> 3) & 1) * 8 + (lane & 7)) * A2_LDB
                                       + (lane >> 4) * 16);

    // ---- hoist Q fragments into registers (loop-invariant) ----
    uint32_t qreg[8][4], qlreg[8][4];
    {
        CP_WAIT(2);          // Q group done (2 K/V groups still in flight)
        __syncthreads();
#pragma unroll
        for (int ks = 0; ks < 8; ks++) {
            ldm_x4(qreg[ks],  sb + A2_QH + q_off + ks * 32);
            ldm_x4(qlreg[ks], sb + A2_QL + q_off + ks * 32);
        }
    }

    const float* biasR0 = Bias + ((size_t)bh * PS + q0 + warp * 16 + (lane >> 2)) * PS;
    const float* biasR1 = biasR0 + 8 * PS;
    const int bcol = (lane & 3) * 2;

    float o[16][4];
#pragma unroll
    for (int nd = 0; nd < 16; nd++)
#pragma unroll
        for (int j = 0; j < 4; j++) o[nd][j] = 0.0f;
    float lacc[4] = {0.0f, 0.0f, 0.0f, 0.0f};
    float m0 = -1e30f, m1 = -1e30f;
    const uint32_t ONESB[2] = {0x3C003C00u, 0x3C003C00u};

    float2 nb0[4], nb1[4];
#pragma unroll
    for (int nf = 0; nf < 4; nf++) {
        nb0[nf] = *(const float2*)(biasR0 + nf * 8 + bcol);
        nb1[nf] = *(const float2*)(biasR1 + nf * 8 + bcol);
    }

    const int NT = PS / 32;   // 64 tiles
    for (int t = 0; t < NT; t++) {
        if (t < NT - 1) { CP_WAIT(1); } else { CP_WAIT(0); }
        __syncthreads();

        const uint32_t st = sb + A2_ST0 + (t % 3) * A2_STAGE;

        float sc[4][4];
#pragma unroll
        for (int nf = 0; nf < 4; nf++) {
            sc[nf][0] = nb0[nf].x; sc[nf][1] = nb0[nf].y;
            sc[nf][2] = nb1[nf].x; sc[nf][3] = nb1[nf].y;
        }
        if (t + 1 < NT) {
            const int k1 = (t + 1) * 32;
#pragma unroll
            for (int nf = 0; nf < 4; nf++) {
                nb0[nf] = *(const float2*)(biasR0 + k1 + nf * 8 + bcol);
                nb1[nf] = *(const float2*)(biasR1 + k1 + nf * 8 + bcol);
            }
        }

        // ---- scores += Q K^T (split 3-combo), Q from registers ----
#pragma unroll
        for (int ks = 0; ks < 8; ks++) {
#pragma unroll
            for (int nf2 = 0; nf2 < 2; nf2++) {
                uint32_t kbh[4], kbl[4];
                ldm_x4(kbh, st + k4_off + nf2 * 16 * A2_LDB + ks * 32);
                ldm_x4(kbl, st + A2_TILE + k4_off + nf2 * 16 * A2_LDB + ks * 32);
                mma_bf16(sc[2*nf2],   qreg[ks],  kbh);
                mma_bf16(sc[2*nf2+1], qreg[ks],  kbh + 2);
                mma_bf16(sc[2*nf2],   qreg[ks],  kbl);
                mma_bf16(sc[2*nf2+1], qreg[ks],  kbl + 2);
                mma_bf16(sc[2*nf2],   qlreg[ks], kbh);
                mma_bf16(sc[2*nf2+1], qlreg[ks], kbh + 2);
            }
        }

        // ---- online softmax: max ----
        float mx0 = sc[0][0], mx1 = sc[0][2];
#pragma unroll
        for (int nf = 0; nf < 4; nf++) {
            mx0 = fmaxf(mx0, fmaxf(sc[nf][0], sc[nf][1]));
            mx1 = fmaxf(mx1, fmaxf(sc[nf][2], sc[nf][3]));
        }
        mx0 = fmaxf(mx0, __shfl_xor_sync(0xffffffffu, mx0, 1));
        mx0 = fmaxf(mx0, __shfl_xor_sync(0xffffffffu, mx0, 2));
        mx1 = fmaxf(mx1, __shfl_xor_sync(0xffffffffu, mx1, 1));
        mx1 = fmaxf(mx1, __shfl_xor_sync(0xffffffffu, mx1, 2));
        const float mn0 = fmaxf(m0, mx0), mn1 = fmaxf(m1, mx1);
        const float mL0 = mn0 * L2E, mL1 = mn1 * L2E;
        const float al0 = ex2f((m0 - mn0) * L2E);
        const float al1 = ex2f((m1 - mn1) * L2E);
        m0 = mn0; m1 = mn1;

        if (al0 != 1.0f || al1 != 1.0f) {
#pragma unroll
            for (int nd = 0; nd < 16; nd++) {
                o[nd][0] *= al0; o[nd][1] *= al0;
                o[nd][2] *= al1; o[nd][3] *= al1;
            }
            lacc[0] *= al0; lacc[1] *= al0;
            lacc[2] *= al1; lacc[3] *= al1;
        }

        // ---- PV: P exp/pack per 16-key group, then its MMAs ----
#pragma unroll
        for (int j2 = 0; j2 < 2; j2++) {
            const int f0 = 2 * j2, f1 = f0 + 1;
            uint32_t pf[4];
            pf[0] = h2ex2(fmaf(sc[f0][0], L2E, -mL0), fmaf(sc[f0][1], L2E, -mL0));
            pf[1] = h2ex2(fmaf(sc[f0][2], L2E, -mL1), fmaf(sc[f0][3], L2E, -mL1));
            pf[2] = h2ex2(fmaf(sc[f1][0], L2E, -mL0), fmaf(sc[f1][1], L2E, -mL0));
            pf[3] = h2ex2(fmaf(sc[f1][2], L2E, -mL1), fmaf(sc[f1][3], L2E, -mL1));
            mma_f16(lacc, pf, ONESB);
            const uint32_t vrow = st + 2 * A2_TILE + v4_off + j2 * 16 * A2_LDB;
#pragma unroll
            for (int nd2 = 0; nd2 < 8; nd2++) {
                uint32_t vbh[4];
                ldm_x4t(vbh, vrow + nd2 * 32);
                mma_f16(o[2*nd2],   pf, vbh);
                mma_f16(o[2*nd2+1], pf, vbh + 2);
            }
        }

        if (t + 2 < NT) {
            load_stage((t + 2) % 3, t + 2);
            CP_COMMIT();
        }
    }

    // ---- epilogue: normalize, split fp16, store ctx ----
    const float inv0 = 1.0f / lacc[0], inv1 = 1.0f / lacc[2];
    const int rg0 = q0 + warp * 16 + (lane >> 2);
    __half* och = Ch + base;
    __half* ocl = Cl + base;
#pragma unroll
    for (int nd = 0; nd < 16; nd++) {
        const int col = nd * 8 + (lane & 3) * 2;
        uint32_t hp, lp;
        packsplit_f16(o[nd][0] * inv0, o[nd][1] * inv0, hp, lp);
        *(uint32_t*)(och + (size_t)rg0 * PHID + col) = hp;
        *(uint32_t*)(ocl + (size_t)rg0 * PHID + col) = lp;
        packsplit_f16(o[nd][2] * inv1, o[nd][3] * inv1, hp, lp);
        *(uint32_t*)(och + (size_t)(rg0 + 8) * PHID + col) = hp;
        *(uint32_t*)(ocl + (size_t)(rg0 + 8) * PHID + col) = lp;
    }
}

// ---------------------------------------------------------------------------
extern "C" void kernel_launch(void* const* d_in, const int* in_sizes, int n_in,
                              void* d_out, int out_size)
{
    (void)in_sizes; (void)n_in; (void)out_size;
    const float* x    = (const float*)d_in[0];
    const float* bias = (const float*)d_in[1];
    const float* Wq   = (const float*)d_in[2];
    const float* bq   = (const float*)d_in[3];
    const float* Wk   = (const float*)d_in[4];
    const float* bk   = (const float*)d_in[5];
    const float* Wv   = (const float*)d_in[6];
    const float* bv   = (const float*)d_in[7];
    const float* Wo   = (const float*)d_in[8];
    const float* bo   = (const float*)d_in[9];
    float* out = (float*)d_out;

    __nv_bfloat16 *xh, *xl, *qh, *ql, *kh, *kl;
    __half *xh2, *xl2, *vhf, *ch2, *cl2, *wvt, *wot;
    __nv_bfloat16 *wqh, *wql, *wkh, *wkl;
    cudaGetSymbolAddress((void**)&xh, g_xh);
    cudaGetSymbolAddress((void**)&xl, g_xl);
    cudaGetSymbolAddress((void**)&xh2, g_xh2);
    cudaGetSymbolAddress((void**)&xl2, g_xl2);
    cudaGetSymbolAddress((void**)&qh, g_qh);
    cudaGetSymbolAddress((void**)&ql, g_ql);
    cudaGetSymbolAddress((void**)&kh, g_kh);
    cudaGetSymbolAddress((void**)&kl, g_kl);
    cudaGetSymbolAddress((void**)&vhf, g_vhf);
    cudaGetSymbolAddress((void**)&ch2, g_ch2);
    cudaGetSymbolAddress((void**)&cl2, g_cl2);
    cudaGetSymbolAddress((void**)&wqh, g_wqh);
    cudaGetSymbolAddress((void**)&wql, g_wql);
    cudaGetSymbolAddress((void**)&wkh, g_wkh);
    cudaGetSymbolAddress((void**)&wkl, g_wkl);
    cudaGetSymbolAddress((void**)&wvt, g_wvt);
    cudaGetSymbolAddress((void**)&wot, g_wot);

    static bool attr_set = false;
    if (!attr_set) {
        cudaFuncSetAttribute(gemm_qk,
                             cudaFuncAttributeMaxDynamicSharedMemorySize, QK_SMEM);
        cudaFuncSetAttribute(gemm_f16_2c,
                             cudaFuncAttributeMaxDynamicSharedMemorySize, GSMEM2);
        cudaFuncSetAttribute(attn_mma,
                             cudaFuncAttributeMaxDynamicSharedMemorySize, A2_SMEM);
        attr_set = true;
    }

    // 1) conversions
    {
        int n4 = PM * PHID / 4;
        split_x_kernel<<<(n4 + 255) / 256, 256>>>(x, xh, xl, xh2, xl2, n4);
        dim3 tg(PHID / 32, PHID / 32, 4);
        dim3 tb(32, 8);
        transpose_all_kernel<<<tg, tb>>>(Wq, Wk, Wv, Wo,
                                         wqh, wql, wkh, wkl, wvt, wot);
    }

    // 2) projections
    dim3 qkgrid(2 * PHID / 128, PM / 128);    // (32, 32)
    gemm_qk<<<qkgrid, 256, QK_SMEM>>>(xh, xl, wqh, wql, wkh, wkl,
                                      bq, bk, qh, ql, kh, kl);
    dim3 vgrid(PHID / 128, PM / 128);         // (16, 32)
    gemm_f16_2c<<<vgrid, 256, GSMEM2>>>(xh2, xl2, wvt, bv, nullptr, vhf);

    // 3) tensor-core attention (2 CTAs/SM, Q in regs) -> split fp16 ctx
    dim3 agrid(PS / 64, PB * PH);             // (32, 32)
    attn_mma<<<agrid, 128, A2_SMEM>>>(qh, ql, kh, kl, vhf, bias, ch2, cl2);

    // 4) output projection -> fp32 out
    gemm_f16_2c<<<vgrid, 256, GSMEM2>>>(ch2, cl2, wot, bo, out, nullptr);
}

// round 17
// speedup vs baseline: 1.0994x; 1.0254x over previous
#include <cuda_runtime.h>
#include <cuda_bf16.h>
#include <cuda_fp16.h>
#include <math.h>
#include <stdint.h>

// Problem constants
#define PB   2
#define PS   2048
#define PHID 2048
#define PH   16
#define PD   128
#define PM   (PB * PS)          // 4096 rows
#define QSCALE 11.313708498984760f   // sqrt(128)

// ---------------------------------------------------------------------------
// Scratch (no cudaMalloc allowed)
// ---------------------------------------------------------------------------
__device__ __nv_bfloat16 g_xh[(size_t)PM * PHID];    // x split bf16 (QK path)
__device__ __nv_bfloat16 g_xl[(size_t)PM * PHID];
__device__ __half        g_xh2[(size_t)PM * PHID];   // x split fp16 (V path)
__device__ __half        g_xl2[(size_t)PM * PHID];
__device__ __nv_bfloat16 g_qh[(size_t)PM * PHID];
__device__ __nv_bfloat16 g_ql[(size_t)PM * PHID];
__device__ __nv_bfloat16 g_kh[(size_t)PM * PHID];
__device__ __nv_bfloat16 g_kl[(size_t)PM * PHID];
__device__ __half        g_vhf[(size_t)PM * PHID];   // V, fp16
__device__ __half        g_ch2[(size_t)PM * PHID];   // ctx split fp16
__device__ __half        g_cl2[(size_t)PM * PHID];

// transposed weights [N,K]
__device__ __nv_bfloat16 g_wqh[(size_t)PHID * PHID];
__device__ __nv_bfloat16 g_wql[(size_t)PHID * PHID];
__device__ __nv_bfloat16 g_wkh[(size_t)PHID * PHID];
__device__ __nv_bfloat16 g_wkl[(size_t)PHID * PHID];
__device__ __half        g_wvt[(size_t)PHID * PHID]; // Wv^T single fp16
__device__ __half        g_wot[(size_t)PHID * PHID]; // Wo^T single fp16

// ---------------------------------------------------------------------------
// Helpers
// ---------------------------------------------------------------------------
__device__ __forceinline__ uint32_t smem_u32(const void* p) {
    uint32_t a;
    asm("{ .reg .u64 t; cvta.to.shared.u64 t, %1; cvt.u32.u64 %0, t; }"
        : "=r"(a) : "l"(p));
    return a;
}

__device__ __forceinline__ void cp16(uint32_t s, const void* g) {
    asm volatile("cp.async.cg.shared.global [%0], [%1], 16;" :: "r"(s), "l"(g));
}
#define CP_COMMIT() asm volatile("cp.async.commit_group;" ::: "memory")
#define CP_WAIT(n)  asm volatile("cp.async.wait_group %0;" :: "n"(n) : "memory")

__device__ __forceinline__ void ldm_x4(uint32_t* r, uint32_t addr) {
    asm volatile("ldmatrix.sync.aligned.m8n8.x4.shared.b16 {%0,%1,%2,%3}, [%4];"
                 : "=r"(r[0]), "=r"(r[1]), "=r"(r[2]), "=r"(r[3]) : "r"(addr));
}
__device__ __forceinline__ void ldm_x4t(uint32_t* r, uint32_t addr) {
    asm volatile("ldmatrix.sync.aligned.m8n8.x4.trans.shared.b16 {%0,%1,%2,%3}, [%4];"
                 : "=r"(r[0]), "=r"(r[1]), "=r"(r[2]), "=r"(r[3]) : "r"(addr));
}
__device__ __forceinline__ void mma_bf16(float* c, const uint32_t* a, const uint32_t* b) {
    asm volatile(
        "mma.sync.aligned.m16n8k16.row.col.f32.bf16.bf16.f32 "
        "{%0,%1,%2,%3}, {%4,%5,%6,%7}, {%8,%9}, {%0,%1,%2,%3};"
        : "+f"(c[0]), "+f"(c[1]), "+f"(c[2]), "+f"(c[3])
        : "r"(a[0]), "r"(a[1]), "r"(a[2]), "r"(a[3]), "r"(b[0]), "r"(b[1]));
}
__device__ __forceinline__ void mma_f16(float* c, const uint32_t* a, const uint32_t* b) {
    asm volatile(
        "mma.sync.aligned.m16n8k16.row.col.f32.f16.f16.f32 "
        "{%0,%1,%2,%3}, {%4,%5,%6,%7}, {%8,%9}, {%0,%1,%2,%3};"
        : "+f"(c[0]), "+f"(c[1]), "+f"(c[2]), "+f"(c[3])
        : "r"(a[0]), "r"(a[1]), "r"(a[2]), "r"(a[3]), "r"(b[0]), "r"(b[1]));
}

__device__ __forceinline__ float ex2f(float x) {
    float r;
    asm("ex2.approx.f32 %0, %1;" : "=f"(r) : "f"(x));
    return r;
}

// pack two fp32 exponent args into f16x2 and take 2^x on both at once
__device__ __forceinline__ uint32_t h2ex2(float y0, float y1) {
    uint32_t h, p;
    asm("cvt.rn.f16x2.f32 %0, %1, %2;" : "=r"(h) : "f"(y1), "f"(y0));
    asm("ex2.approx.f16x2 %0, %1;" : "=r"(p) : "r"(h));
    return p;
}

// Fast RNE split of two floats into (hi bf16x2, lo bf16x2).
__device__ __forceinline__ void packsplit(float a, float b, uint32_t& hp, uint32_t& lp) {
    asm("cvt.rn.bf16x2.f32 %0, %1, %2;" : "=r"(hp) : "f"(b), "f"(a));
    float ah = __uint_as_float(hp << 16);
    float bh = __uint_as_float(hp & 0xFFFF0000u);
    float la = a - ah;
    float lb = b - bh;
    asm("cvt.rn.bf16x2.f32 %0, %1, %2;" : "=r"(lp) : "f"(lb), "f"(la));
}

// RNE split of two floats into (hi f16x2, lo f16x2).
__device__ __forceinline__ void packsplit_f16(float a, float b, uint32_t& hp, uint32_t& lp) {
    __half2 h = __floats2half2_rn(a, b);
    float la = a - __half2float(__low2half(h));
    float lb = b - __half2float(__high2half(h));
    __half2 l = __floats2half2_rn(la, lb);
    hp = *reinterpret_cast<uint32_t*>(&h);
    lp = *reinterpret_cast<uint32_t*>(&l);
}

// ---------------------------------------------------------------------------
// Conversion kernels
// ---------------------------------------------------------------------------
__global__ void split_x_kernel(const float* __restrict__ in,
                               __nv_bfloat16* __restrict__ hb,
                               __nv_bfloat16* __restrict__ lb,
                               __half* __restrict__ hf,
                               __half* __restrict__ lf, int n4)
{
    int i = blockIdx.x * blockDim.x + threadIdx.x;
    if (i >= n4) return;
    float4 v = ((const float4*)in)[i];
    uint32_t h0, l0, h1, l1;
    packsplit(v.x, v.y, h0, l0);
    packsplit(v.z, v.w, h1, l1);
    ((uint32_t*)hb)[2*i]   = h0;
    ((uint32_t*)hb)[2*i+1] = h1;
    ((uint32_t*)lb)[2*i]   = l0;
    ((uint32_t*)lb)[2*i+1] = l1;
    packsplit_f16(v.x, v.y, h0, l0);
    packsplit_f16(v.z, v.w, h1, l1);
    ((uint32_t*)hf)[2*i]   = h0;
    ((uint32_t*)hf)[2*i+1] = h1;
    ((uint32_t*)lf)[2*i]   = l0;
    ((uint32_t*)lf)[2*i+1] = l1;
}

// One launch transposes all 4 weight matrices.  z=0,1 -> bf16 split (Wq, Wk);
// z=2,3 -> single fp16 (Wv, Wo).
__global__ void transpose_all_kernel(
    const float* __restrict__ Wq, const float* __restrict__ Wk,
    const float* __restrict__ Wv, const float* __restrict__ Wo,
    __nv_bfloat16* __restrict__ Tqh, __nv_bfloat16* __restrict__ Tql,
    __nv_bfloat16* __restrict__ Tkh, __nv_bfloat16* __restrict__ Tkl,
    __half* __restrict__ Tv, __half* __restrict__ To)
{
    __shared__ float t[32][33];
    int z = blockIdx.z;
    const float* W = (z == 0) ? Wq : (z == 1) ? Wk : (z == 2) ? Wv : Wo;
    int n0 = blockIdx.x * 32, k0 = blockIdx.y * 32;
    int tx = threadIdx.x, ty0 = threadIdx.y;   // 32 x 8
#pragma unroll
    for (int j = 0; j < 32; j += 8)
        t[ty0 + j][tx] = W[(size_t)(k0 + ty0 + j) * PHID + n0 + tx];
    __syncthreads();
#pragma unroll
    for (int j = 0; j < 32; j += 8) {
        int n = ty0 + j;
        float v = t[tx][n];
        size_t o = (size_t)(n0 + n) * PHID + k0 + tx;
        if (z < 2) {
            __nv_bfloat16 h = __float2bfloat16(v);
            __nv_bfloat16 l = __float2bfloat16(v - __bfloat162float(h));
            if (z == 0) { Tqh[o] = h; Tql[o] = l; }
            else        { Tkh[o] = h; Tkl[o] = l; }
        } else {
            __half h = __float2half_rn(v);
            if (z == 2) Tv[o] = h; else To[o] = h;
        }
    }
}

// ---------------------------------------------------------------------------
// GEMM tile configs
// ---------------------------------------------------------------------------
// Q/K path: 4-stage BK=16 ring, tile = 128 rows x 48B
#define QK_TILE  6144
#define QK_AH    0
#define QK_AL    (QK_TILE)
#define QK_BH    (2 * QK_TILE)
#define QK_BL    (3 * QK_TILE)
#define QK_STAGE (4 * QK_TILE)   // 24576
#define QK_SMEM  (4 * QK_STAGE)  // 98304

// V / Wo path: BK=32 tiles of 128 x 80B, 3-stage pipeline
#define LDT   40
#define TILE_B (128 * LDT * 2)   // 10240
#define OFF_AH 0
#define OFF_AL (TILE_B)
#define OFF_BH (2 * TILE_B)
#define STAGE2_B (3 * TILE_B)    // 30720
#define GSMEM2 (3 * STAGE2_B)    // 92160

#define QKV_SMEM 98304           // max(QK_SMEM, GSMEM2)

// ---------------------------------------------------------------------------
// fp16 2-combo GEMM inner (shared by merged QKV kernel's V path and Wo GEMM)
// ---------------------------------------------------------------------------
__device__ __forceinline__ void gemm_f16_body(
    uint32_t sb, int tid, int lane, int warp, int m0, int n0,
    const __half* __restrict__ Ah, const __half* __restrict__ Al,
    const __half* __restrict__ Bt,
    const float* __restrict__ bias, float* __restrict__ Cf,
    __half* __restrict__ Co)
{
    const int wm = warp >> 2;
    const int wn = warp & 3;

    const __half* pAh = Ah + (size_t)m0 * PHID;
    const __half* pAl = Al + (size_t)m0 * PHID;
    const __half* pB  = Bt + (size_t)n0 * PHID;

    const int r0 = tid >> 2;
    const int c0 = (tid & 3) * 8;
    const uint32_t so0 = (uint32_t)(r0 * 80 + (tid & 3) * 16);
    const uint32_t so1 = (uint32_t)((r0 + 64) * 80 + (tid & 3) * 16);

    const uint32_t a_off = (uint32_t)((wm * 64 + (lane & 15)) * 80 + ((lane >> 4) << 4));
    const uint32_t b4_off = (uint32_t)((wn * 32 + ((lane >> 4) << 3) + (lane & 7)) * 80
                                       + ((lane & 8) ? 16 : 0));

    float acc[4][4][4];
#pragma unroll
    for (int mi = 0; mi < 4; mi++)
#pragma unroll
        for (int ni = 0; ni < 4; ni++)
#pragma unroll
            for (int j = 0; j < 4; j++) acc[mi][ni][j] = 0.0f;

    auto load_stage = [&](int stage, int kc) {
        const uint32_t st = sb + stage * STAGE2_B;
        const size_t g0 = (size_t)r0 * PHID + kc * 32 + c0;
        const size_t g1 = (size_t)(r0 + 64) * PHID + kc * 32 + c0;
        cp16(st + OFF_AH + so0, pAh + g0);
        cp16(st + OFF_AH + so1, pAh + g1);
        cp16(st + OFF_AL + so0, pAl + g0);
        cp16(st + OFF_AL + so1, pAl + g1);
        cp16(st + OFF_BH + so0, pB + g0);
        cp16(st + OFF_BH + so1, pB + g1);
    };

    auto compute_stage = [&](int stage) {
        const uint32_t st = sb + stage * STAGE2_B;
#pragma unroll
        for (int ks = 0; ks < 2; ks++) {
            const uint32_t k32 = ks * 32;
            uint32_t bf[4][2], a[4][4];
            ldm_x4(&bf[0][0], st + OFF_BH + b4_off + k32);
            ldm_x4(&bf[2][0], st + OFF_BH + b4_off + 1280 + k32);
#pragma unroll
            for (int mi = 0; mi < 4; mi++)
                ldm_x4(a[mi], st + OFF_AH + a_off + mi * 1280 + k32);
#pragma unroll
            for (int mi = 0; mi < 4; mi++)
#pragma unroll
                for (int ni = 0; ni < 4; ni++)
                    mma_f16(acc[mi][ni], a[mi], bf[ni]);
#pragma unroll
            for (int mi = 0; mi < 4; mi++)
                ldm_x4(a[mi], st + OFF_AL + a_off + mi * 1280 + k32);
#pragma unroll
            for (int mi = 0; mi < 4; mi++)
#pragma unroll
                for (int ni = 0; ni < 4; ni++)
                    mma_f16(acc[mi][ni], a[mi], bf[ni]);
        }
    };

    load_stage(0, 0);
    CP_COMMIT();
    load_stage(1, 1);
    CP_COMMIT();
    const int NKC = PHID / 32;   // 64
    for (int kc = 0; kc < NKC; kc++) {
        if (kc < NKC - 1) { CP_WAIT(1); } else { CP_WAIT(0); }
        __syncthreads();
        compute_stage(kc % 3);
        if (kc + 2 < NKC) {
            load_stage((kc + 2) % 3, kc + 2);
            CP_COMMIT();
        }
    }

#pragma unroll
    for (int mi = 0; mi < 4; mi++) {
        const int row = m0 + wm * 64 + mi * 16 + (lane >> 2);
#pragma unroll
        for (int ni = 0; ni < 4; ni++) {
            const int col = n0 + wn * 32 + ni * 8 + (lane & 3) * 2;
            const float b0 = bias[col], b1 = bias[col + 1];
            float v00 = acc[mi][ni][0] + b0;
            float v01 = acc[mi][ni][1] + b1;
            float v10 = acc[mi][ni][2] + b0;
            float v11 = acc[mi][ni][3] + b1;
            if (Cf) {
                *(float2*)(Cf + (size_t)row * PHID + col)       = make_float2(v00, v01);
                *(float2*)(Cf + (size_t)(row + 8) * PHID + col) = make_float2(v10, v11);
            } else {
                __half2 p0 = __floats2half2_rn(v00, v01);
                __half2 p1 = __floats2half2_rn(v10, v11);
                *(uint32_t*)(Co + (size_t)row * PHID + col) =
                    *reinterpret_cast<uint32_t*>(&p0);
                *(uint32_t*)(Co + (size_t)(row + 8) * PHID + col) =
                    *reinterpret_cast<uint32_t*>(&p1);
            }
        }
    }
}

// ---------------------------------------------------------------------------
// Merged QKV projection launch.  sel = blockIdx.x>>4: 0=Q, 1=K (split-bf16,
// BK=16 4-stage ring), 2=V (fp16 2-combo, BK=32 3-stage).  One grid =
// better wave packing than two sequential launches.
// ---------------------------------------------------------------------------
__global__ __launch_bounds__(256, 2) void gemm_qkv(
    const __nv_bfloat16* __restrict__ Ah, const __nv_bfloat16* __restrict__ Al,
    const __half* __restrict__ Ah2, const __half* __restrict__ Al2,
    const __nv_bfloat16* __restrict__ Wqh, const __nv_bfloat16* __restrict__ Wql,
    const __nv_bfloat16* __restrict__ Wkh, const __nv_bfloat16* __restrict__ Wkl,
    const __half* __restrict__ Wvt,
    const float* __restrict__ bq, const float* __restrict__ bk,
    const float* __restrict__ bv,
    __nv_bfloat16* __restrict__ Qh, __nv_bfloat16* __restrict__ Ql,
    __nv_bfloat16* __restrict__ Kh, __nv_bfloat16* __restrict__ Kl,
    __half* __restrict__ Vhf)
{
    extern __shared__ char smem[];
    const uint32_t sb = smem_u32(smem);
    const int tid  = threadIdx.x;
    const int lane = tid & 31;
    const int warp = tid >> 5;
    const int sel = blockIdx.x >> 4;            // 0=Q 1=K 2=V
    const int n0  = (blockIdx.x & 15) * 128;
    const int m0  = blockIdx.y * 128;

    if (sel == 2) {
        gemm_f16_body(sb, tid, lane, warp, m0, n0,
                      Ah2, Al2, Wvt, bv, nullptr, Vhf);
        return;
    }

    const int wm = warp >> 2;
    const int wn = warp & 3;
    const __nv_bfloat16* Bh = sel ? Wkh : Wqh;
    const __nv_bfloat16* Bl = sel ? Wkl : Wql;
    const float* bias = sel ? bk : bq;
    const float scale = sel ? 1.0f : QSCALE;

    const __nv_bfloat16* pAh = Ah + (size_t)m0 * PHID;
    const __nv_bfloat16* pAl = Al + (size_t)m0 * PHID;
    const __nv_bfloat16* pBh = Bh + (size_t)n0 * PHID;
    const __nv_bfloat16* pBl = Bl + (size_t)n0 * PHID;

    const int r0 = tid >> 1;               // 0..127
    const int ce = (tid & 1) * 8;
    const uint32_t so = (uint32_t)(r0 * 48 + (tid & 1) * 16);

    const uint32_t a_off = (uint32_t)((wm * 64 + (lane & 15)) * 48 + ((lane >> 4) << 4));
    const uint32_t b4_off = (uint32_t)((wn * 32 + ((lane >> 4) << 3) + (lane & 7)) * 48
                                       + ((lane & 8) ? 16 : 0));

    float acc[4][4][4];
#pragma unroll
    for (int mi = 0; mi < 4; mi++)
#pragma unroll
        for (int ni = 0; ni < 4; ni++)
#pragma unroll
            for (int j = 0; j < 4; j++) acc[mi][ni][j] = 0.0f;

    auto load_stage = [&](int stage, int kc) {
        const uint32_t st = sb + stage * QK_STAGE;
        const size_t g = (size_t)r0 * PHID + kc * 16 + ce;
        cp16(st + QK_AH + so, pAh + g);
        cp16(st + QK_AL + so, pAl + g);
        cp16(st + QK_BH + so, pBh + g);
        cp16(st + QK_BL + so, pBl + g);
    };

    auto compute_stage = [&](int stage) {
        const uint32_t st = sb + stage * QK_STAGE;
        uint32_t bh0[4], bh1[4], bl0[4], bl1[4], a[4][4];
        ldm_x4(bh0, st + QK_BH + b4_off);
        ldm_x4(bh1, st + QK_BH + b4_off + 768);
        ldm_x4(bl0, st + QK_BL + b4_off);
        ldm_x4(bl1, st + QK_BL + b4_off + 768);
#pragma unroll
        for (int mi = 0; mi < 4; mi++)
            ldm_x4(a[mi], st + QK_AH + a_off + mi * 768);
#pragma unroll
        for (int mi = 0; mi < 4; mi++) {
            mma_bf16(acc[mi][0], a[mi], bh0);
            mma_bf16(acc[mi][1], a[mi], bh0 + 2);
            mma_bf16(acc[mi][2], a[mi], bh1);
            mma_bf16(acc[mi][3], a[mi], bh1 + 2);
        }
#pragma unroll
        for (int mi = 0; mi < 4; mi++) {
            mma_bf16(acc[mi][0], a[mi], bl0);
            mma_bf16(acc[mi][1], a[mi], bl0 + 2);
            mma_bf16(acc[mi][2], a[mi], bl1);
            mma_bf16(acc[mi][3], a[mi], bl1 + 2);
        }
#pragma unroll
        for (int mi = 0; mi < 4; mi++)
            ldm_x4(a[mi], st + QK_AL + a_off + mi * 768);
#pragma unroll
        for (int mi = 0; mi < 4; mi++) {
            mma_bf16(acc[mi][0], a[mi], bh0);
            mma_bf16(acc[mi][1], a[mi], bh0 + 2);
            mma_bf16(acc[mi][2], a[mi], bh1);
            mma_bf16(acc[mi][3], a[mi], bh1 + 2);
        }
    };

    load_stage(0, 0);
    CP_COMMIT();
    load_stage(1, 1);
    CP_COMMIT();
    load_stage(2, 2);
    CP_COMMIT();
    const int NKC = PHID / 16;   // 128
    for (int kc = 0; kc < NKC; kc++) {
        if (kc < NKC - 2)      { CP_WAIT(2); }
        else if (kc == NKC - 2){ CP_WAIT(1); }
        else                   { CP_WAIT(0); }
        __syncthreads();
        compute_stage(kc & 3);
        if (kc + 3 < NKC) {
            load_stage((kc + 3) & 3, kc + 3);
            CP_COMMIT();
        }
    }

    __nv_bfloat16* Oh = sel ? Kh : Qh;
    __nv_bfloat16* Ol = sel ? Kl : Ql;
#pragma unroll
    for (int mi = 0; mi < 4; mi++) {
        const int row = m0 + wm * 64 + mi * 16 + (lane >> 2);
#pragma unroll
        for (int ni = 0; ni < 4; ni++) {
            const int col = n0 + wn * 32 + ni * 8 + (lane & 3) * 2;
            const float b0 = bias[col], b1 = bias[col + 1];
            float v00 = (acc[mi][ni][0] + b0) * scale;
            float v01 = (acc[mi][ni][1] + b1) * scale;
            float v10 = (acc[mi][ni][2] + b0) * scale;
            float v11 = (acc[mi][ni][3] + b1) * scale;
            uint32_t hp, lp;
            packsplit(v00, v01, hp, lp);
            *(uint32_t*)(Oh + (size_t)row * PHID + col) = hp;
            *(uint32_t*)(Ol + (size_t)row * PHID + col) = lp;
            packsplit(v10, v11, hp, lp);
            *(uint32_t*)(Oh + (size_t)(row + 8) * PHID + col) = hp;
            *(uint32_t*)(Ol + (size_t)(row + 8) * PHID + col) = lp;
        }
    }
}

// ---------------------------------------------------------------------------
// Wo projection GEMM (fp16 2-combo, fp32 out) — standalone launch.
// ---------------------------------------------------------------------------
__global__ __launch_bounds__(256, 2) void gemm_f16_2c(
    const __half* __restrict__ Ah, const __half* __restrict__ Al,
    const __half* __restrict__ Bt,
    const float* __restrict__ bias, float* __restrict__ Cf)
{
    extern __shared__ char smem[];
    const uint32_t sb = smem_u32(smem);
    const int tid  = threadIdx.x;
    gemm_f16_body(sb, tid, tid & 31, tid >> 5,
                  blockIdx.y * 128, blockIdx.x * 128,
                  Ah, Al, Bt, bias, Cf, nullptr);
}

// ---------------------------------------------------------------------------
// Tensor-core flash attention, 2 CTAs/SM, Q held in REGISTERS (loop-invariant).
// CTA = 128 threads (4 warps), 64 q-rows, 32-key K/V tiles, 3-stage ring.
// ---------------------------------------------------------------------------
#define A2_LDB  272
#define A2_QH   0
#define A2_QL   (64 * A2_LDB)             // 17408
#define A2_ST0  (2 * 64 * A2_LDB)         // 34816
#define A2_TILE (32 * A2_LDB)             // 8704
#define A2_STAGE (3 * A2_TILE)            // 26112
#define A2_SMEM (A2_ST0 + 3 * A2_STAGE)   // 113152

__global__ __launch_bounds__(128, 2) void attn_mma(
    const __nv_bfloat16* __restrict__ Qh, const __nv_bfloat16* __restrict__ Ql,
    const __nv_bfloat16* __restrict__ Kh, const __nv_bfloat16* __restrict__ Kl,
    const __half* __restrict__ Vh,
    const float* __restrict__ Bias,
    __half* __restrict__ Ch, __half* __restrict__ Cl)
{
    extern __shared__ char smem[];
    const uint32_t sb = smem_u32(smem);
    const int tid = threadIdx.x;
    const int lane = tid & 31;
    const int warp = tid >> 5;          // 0..3
    const int bh = blockIdx.y;
    const int b  = bh >> 4;
    const int h  = bh & 15;
    const int q0 = blockIdx.x * 64;
    const float L2E = 1.44269504f;

    const size_t base = (size_t)b * PS * PHID + (size_t)h * PD;
    const __nv_bfloat16* pQh = Qh + base + (size_t)q0 * PHID;
    const __nv_bfloat16* pQl = Ql + base + (size_t)q0 * PHID;
    const __nv_bfloat16* pKh = Kh + base;
    const __nv_bfloat16* pKl = Kl + base;
    const __half* pVh = Vh + base;

    // Q loader (into smem; consumed once into registers below)
    {
        const int r = tid >> 1;
        const int ce = (tid & 1) * 64;
        const uint32_t so = (uint32_t)(r * A2_LDB + (tid & 1) * 128);
#pragma unroll
        for (int i = 0; i < 8; i++) {
            cp16(sb + A2_QH + so + i * 16, pQh + (size_t)r * PHID + ce + i * 8);
            cp16(sb + A2_QL + so + i * 16, pQl + (size_t)r * PHID + ce + i * 8);
        }
    }
    CP_COMMIT();

    // K/V stage loader (3 tiles of 32 rows: Kh, Kl, Vh)
    const int kvr  = tid >> 2;
    const int kvce = (tid & 3) * 32;
    const uint32_t kvso = (uint32_t)(kvr * A2_LDB + (tid & 3) * 64);
    auto load_stage = [&](int stage, int t) {
        const uint32_t st = sb + A2_ST0 + stage * A2_STAGE;
        const size_t g = (size_t)(t * 32 + kvr) * PHID + kvce;
#pragma unroll
        for (int i = 0; i < 4; i++) {
            cp16(st + kvso + i * 16,               pKh + g + i * 8);
            cp16(st + A2_TILE + kvso + i * 16,     pKl + g + i * 8);
            cp16(st + 2 * A2_TILE + kvso + i * 16, pVh + g + i * 8);
        }
    };

    load_stage(0, 0);
    CP_COMMIT();
    load_stage(1, 1);
    CP_COMMIT();

    const uint32_t q_off = (uint32_t)((warp * 16 + (lane & 15)) * A2_LDB + ((lane >> 4) << 4));
    const uint32_t k4_off = (uint32_t)((((lane >> 4) << 3) + (lane & 7)) * A2_LDB
                                       + ((lane & 8) ? 16 : 0));
    const uint32_t v4_off = (uint32_t)((((lane >> 3) & 1) * 8 + (lane & 7)) * A2_LDB
                                       + (lane >> 4) * 16);

    // ---- hoist Q fragments into registers (loop-invariant) ----
    uint32_t qreg[8][4], qlreg[8][4];
    {
        CP_WAIT(2);          // Q group done (2 K/V groups still in flight)
        __syncthreads();
#pragma unroll
        for (int ks = 0; ks < 8; ks++) {
            ldm_x4(qreg[ks],  sb + A2_QH + q_off + ks * 32);
            ldm_x4(qlreg[ks], sb + A2_QL + q_off + ks * 32);
        }
    }

    const float* biasR0 = Bias + ((size_t)bh * PS + q0 + warp * 16 + (lane >> 2)) * PS;
    const float* biasR1 = biasR0 + 8 * PS;
    const int bcol = (lane & 3) * 2;

    float o[16][4];
#pragma unroll
    for (int nd = 0; nd < 16; nd++)
#pragma unroll
        for (int j = 0; j < 4; j++) o[nd][j] = 0.0f;
    float lacc[4] = {0.0f, 0.0f, 0.0f, 0.0f};
    float m0 = -1e30f, m1 = -1e30f;
    const uint32_t ONESB[2] = {0x3C003C00u, 0x3C003C00u};

    float2 nb0[4], nb1[4];
#pragma unroll
    for (int nf = 0; nf < 4; nf++) {
        nb0[nf] = *(const float2*)(biasR0 + nf * 8 + bcol);
        nb1[nf] = *(const float2*)(biasR1 + nf * 8 + bcol);
    }

    const int NT = PS / 32;   // 64 tiles
    for (int t = 0; t < NT; t++) {
        if (t < NT - 1) { CP_WAIT(1); } else { CP_WAIT(0); }
        __syncthreads();

        const uint32_t st = sb + A2_ST0 + (t % 3) * A2_STAGE;

        float sc[4][4];
#pragma unroll
        for (int nf = 0; nf < 4; nf++) {
            sc[nf][0] = nb0[nf].x; sc[nf][1] = nb0[nf].y;
            sc[nf][2] = nb1[nf].x; sc[nf][3] = nb1[nf].y;
        }
        if (t + 1 < NT) {
            const int k1 = (t + 1) * 32;
#pragma unroll
            for (int nf = 0; nf < 4; nf++) {
                nb0[nf] = *(const float2*)(biasR0 + k1 + nf * 8 + bcol);
                nb1[nf] = *(const float2*)(biasR1 + k1 + nf * 8 + bcol);
            }
        }

        // ---- scores += Q K^T (split 3-combo), Q from registers ----
#pragma unroll
        for (int ks = 0; ks < 8; ks++) {
#pragma unroll
            for (int nf2 = 0; nf2 < 2; nf2++) {
                uint32_t kbh[4], kbl[4];
                ldm_x4(kbh, st + k4_off + nf2 * 16 * A2_LDB + ks * 32);
                ldm_x4(kbl, st + A2_TILE + k4_off + nf2 * 16 * A2_LDB + ks * 32);
                mma_bf16(sc[2*nf2],   qreg[ks],  kbh);
                mma_bf16(sc[2*nf2+1], qreg[ks],  kbh + 2);
                mma_bf16(sc[2*nf2],   qreg[ks],  kbl);
                mma_bf16(sc[2*nf2+1], qreg[ks],  kbl + 2);
                mma_bf16(sc[2*nf2],   qlreg[ks], kbh);
                mma_bf16(sc[2*nf2+1], qlreg[ks], kbh + 2);
            }
        }

        // ---- online softmax: max ----
        float mx0 = sc[0][0], mx1 = sc[0][2];
#pragma unroll
        for (int nf = 0; nf < 4; nf++) {
            mx0 = fmaxf(mx0, fmaxf(sc[nf][0], sc[nf][1]));
            mx1 = fmaxf(mx1, fmaxf(sc[nf][2], sc[nf][3]));
        }
        mx0 = fmaxf(mx0, __shfl_xor_sync(0xffffffffu, mx0, 1));
        mx0 = fmaxf(mx0, __shfl_xor_sync(0xffffffffu, mx0, 2));
        mx1 = fmaxf(mx1, __shfl_xor_sync(0xffffffffu, mx1, 1));
        mx1 = fmaxf(mx1, __shfl_xor_sync(0xffffffffu, mx1, 2));
        const float mn0 = fmaxf(m0, mx0), mn1 = fmaxf(m1, mx1);
        const float mL0 = mn0 * L2E, mL1 = mn1 * L2E;
        const float al0 = ex2f((m0 - mn0) * L2E);
        const float al1 = ex2f((m1 - mn1) * L2E);
        m0 = mn0; m1 = mn1;

        if (al0 != 1.0f || al1 != 1.0f) {
#pragma unroll
            for (int nd = 0; nd < 16; nd++) {
                o[nd][0] *= al0; o[nd][1] *= al0;
                o[nd][2] *= al1; o[nd][3] *= al1;
            }
            lacc[0] *= al0; lacc[1] *= al0;
            lacc[2] *= al1; lacc[3] *= al1;
        }

        // ---- PV: P exp/pack per 16-key group, then its MMAs ----
#pragma unroll
        for (int j2 = 0; j2 < 2; j2++) {
            const int f0 = 2 * j2, f1 = f0 + 1;
            uint32_t pf[4];
            pf[0] = h2ex2(fmaf(sc[f0][0], L2E, -mL0), fmaf(sc[f0][1], L2E, -mL0));
            pf[1] = h2ex2(fmaf(sc[f0][2], L2E, -mL1), fmaf(sc[f0][3], L2E, -mL1));
            pf[2] = h2ex2(fmaf(sc[f1][0], L2E, -mL0), fmaf(sc[f1][1], L2E, -mL0));
            pf[3] = h2ex2(fmaf(sc[f1][2], L2E, -mL1), fmaf(sc[f1][3], L2E, -mL1));
            mma_f16(lacc, pf, ONESB);
            const uint32_t vrow = st + 2 * A2_TILE + v4_off + j2 * 16 * A2_LDB;
#pragma unroll
            for (int nd2 = 0; nd2 < 8; nd2++) {
                uint32_t vbh[4];
                ldm_x4t(vbh, vrow + nd2 * 32);
                mma_f16(o[2*nd2],   pf, vbh);
                mma_f16(o[2*nd2+1], pf, vbh + 2);
            }
        }

        if (t + 2 < NT) {
            load_stage((t + 2) % 3, t + 2);
            CP_COMMIT();
        }
    }

    // ---- epilogue: normalize, split fp16, store ctx ----
    const float inv0 = 1.0f / lacc[0], inv1 = 1.0f / lacc[2];
    const int rg0 = q0 + warp * 16 + (lane >> 2);
    __half* och = Ch + base;
    __half* ocl = Cl + base;
#pragma unroll
    for (int nd = 0; nd < 16; nd++) {
        const int col = nd * 8 + (lane & 3) * 2;
        uint32_t hp, lp;
        packsplit_f16(o[nd][0] * inv0, o[nd][1] * inv0, hp, lp);
        *(uint32_t*)(och + (size_t)rg0 * PHID + col) = hp;
        *(uint32_t*)(ocl + (size_t)rg0 * PHID + col) = lp;
        packsplit_f16(o[nd][2] * inv1, o[nd][3] * inv1, hp, lp);
        *(uint32_t*)(och + (size_t)(rg0 + 8) * PHID + col) = hp;
        *(uint32_t*)(ocl + (size_t)(rg0 + 8) * PHID + col) = lp;
    }
}

// ---------------------------------------------------------------------------
extern "C" void kernel_launch(void* const* d_in, const int* in_sizes, int n_in,
                              void* d_out, int out_size)
{
    (void)in_sizes; (void)n_in; (void)out_size;
    const float* x    = (const float*)d_in[0];
    const float* bias = (const float*)d_in[1];
    const float* Wq   = (const float*)d_in[2];
    const float* bq   = (const float*)d_in[3];
    const float* Wk   = (const float*)d_in[4];
    const float* bk   = (const float*)d_in[5];
    const float* Wv   = (const float*)d_in[6];
    const float* bv   = (const float*)d_in[7];
    const float* Wo   = (const float*)d_in[8];
    const float* bo   = (const float*)d_in[9];
    float* out = (float*)d_out;

    __nv_bfloat16 *xh, *xl, *qh, *ql, *kh, *kl;
    __half *xh2, *xl2, *vhf, *ch2, *cl2, *wvt, *wot;
    __nv_bfloat16 *wqh, *wql, *wkh, *wkl;
    cudaGetSymbolAddress((void**)&xh, g_xh);
    cudaGetSymbolAddress((void**)&xl, g_xl);
    cudaGetSymbolAddress((void**)&xh2, g_xh2);
    cudaGetSymbolAddress((void**)&xl2, g_xl2);
    cudaGetSymbolAddress((void**)&qh, g_qh);
    cudaGetSymbolAddress((void**)&ql, g_ql);
    cudaGetSymbolAddress((void**)&kh, g_kh);
    cudaGetSymbolAddress((void**)&kl, g_kl);
    cudaGetSymbolAddress((void**)&vhf, g_vhf);
    cudaGetSymbolAddress((void**)&ch2, g_ch2);
    cudaGetSymbolAddress((void**)&cl2, g_cl2);
    cudaGetSymbolAddress((void**)&wqh, g_wqh);
    cudaGetSymbolAddress((void**)&wql, g_wql);
    cudaGetSymbolAddress((void**)&wkh, g_wkh);
    cudaGetSymbolAddress((void**)&wkl, g_wkl);
    cudaGetSymbolAddress((void**)&wvt, g_wvt);
    cudaGetSymbolAddress((void**)&wot, g_wot);

    static bool attr_set = false;
    if (!attr_set) {
        cudaFuncSetAttribute(gemm_qkv,
                             cudaFuncAttributeMaxDynamicSharedMemorySize, QKV_SMEM);
        cudaFuncSetAttribute(gemm_f16_2c,
                             cudaFuncAttributeMaxDynamicSharedMemorySize, GSMEM2);
        cudaFuncSetAttribute(attn_mma,
                             cudaFuncAttributeMaxDynamicSharedMemorySize, A2_SMEM);
        attr_set = true;
    }

    // 1) conversions
    {
        int n4 = PM * PHID / 4;
        split_x_kernel<<<(n4 + 255) / 256, 256>>>(x, xh, xl, xh2, xl2, n4);
        dim3 tg(PHID / 32, PHID / 32, 4);
        dim3 tb(32, 8);
        transpose_all_kernel<<<tg, tb>>>(Wq, Wk, Wv, Wo,
                                         wqh, wql, wkh, wkl, wvt, wot);
    }

    // 2) merged Q/K/V projections (one launch, better wave packing)
    dim3 qkvgrid(3 * PHID / 128, PM / 128);   // (48, 32) = 1536 CTAs
    gemm_qkv<<<qkvgrid, 256, QKV_SMEM>>>(xh, xl, xh2, xl2,
                                         wqh, wql, wkh, wkl, wvt,
                                         bq, bk, bv,
                                         qh, ql, kh, kl, vhf);

    // 3) tensor-core attention (2 CTAs/SM, Q in regs) -> split fp16 ctx
    dim3 agrid(PS / 64, PB * PH);             // (32, 32)
    attn_mma<<<agrid, 128, A2_SMEM>>>(qh, ql, kh, kl, vhf, bias, ch2, cl2);

    // 4) output projection -> fp32 out
    dim3 ogrid(PHID / 128, PM / 128);         // (16, 32)
    gemm_f16_2c<<<ogrid, 256, GSMEM2>>>(ch2, cl2, wot, bo, out);
}